// round 10
// baseline (speedup 1.0000x reference)
#include <cuda_runtime.h>

#define MPTS 100000
#define KN   27

// Scratch (__device__ globals)
__device__ float g_Qp[MPTS * 64];
__device__ float g_Kb[MPTS * 64];
__device__ float g_Vo[MPTS * 64];
__device__ float g_Wvo[96 * 64];

// ---------------------------------------------------------------------------
// Kernel W: fold W_vo = Wv(96x64) @ Wo(64x64)  -> [96,64]
// ---------------------------------------------------------------------------
__global__ void kW(const float* __restrict__ Wv, const float* __restrict__ Wo)
{
    int t = blockIdx.x * 256 + threadIdx.x;
    if (t < 96 * 64) {
        int row = t >> 6, col = t & 63;
        float s = 0.f;
#pragma unroll 16
        for (int i = 0; i < 64; i++)
            s = fmaf(Wv[row * 64 + i], Wo[i * 64 + col], s);
        g_Wvo[t] = s;
    }
}

// ---------------------------------------------------------------------------
// Kernel A1: 4 points/warp.  a = geo@Wg -> LN -> relu -> q
//            bdy = q@Wb+bb ; Qp = q@Wq ; Kb = q@Wk
// ---------------------------------------------------------------------------
__global__ void __launch_bounds__(256) kA1(
    const float* __restrict__ geo, const float* __restrict__ Wg,
    const float* __restrict__ gam, const float* __restrict__ bet,
    const float* __restrict__ Wb, const float* __restrict__ bb,
    const float* __restrict__ Wq, const float* __restrict__ Wk,
    float* __restrict__ out)
{
    extern __shared__ float sm[];
    float* sWg = sm;            // 4096
    float* sWq = sm + 4096;     // 4096
    float* sWk = sm + 8192;     // 4096
    float* sGm = sm + 12288;    // 64
    float* sBt = sm + 12352;    // 64
    float* sWb = sm + 12416;    // 64
    float* stage = sm + 12480;  // 8 warps * 256

    for (int i = threadIdx.x; i < 4096; i += 256) {
        sWg[i] = Wg[i]; sWq[i] = Wq[i]; sWk[i] = Wk[i];
    }
    if (threadIdx.x < 64) {
        sGm[threadIdx.x] = gam[threadIdx.x];
        sBt[threadIdx.x] = bet[threadIdx.x];
        sWb[threadIdx.x] = Wb[threadIdx.x];
    }
    __syncthreads();

    const int lane = threadIdx.x & 31;
    float* myS = stage + (threadIdx.x >> 5) * 256;
    const int warp = (blockIdx.x * blockDim.x + threadIdx.x) >> 5;
    const int nw   = (gridDim.x * blockDim.x) >> 5;
    const float bb0 = bb[0];
    const float2 gm = *(const float2*)&sGm[2 * lane];
    const float2 bt = *(const float2*)&sBt[2 * lane];
    const float2 wb = *(const float2*)&sWb[2 * lane];

    for (int p4 = warp * 4; p4 < MPTS; p4 += nw * 4) {
        {
            const float4* gsrc = (const float4*)(geo + (size_t)p4 * 64);
            float4* sdst = (float4*)myS;
            sdst[lane]      = gsrc[lane];
            sdst[lane + 32] = gsrc[lane + 32];
        }
        __syncwarp();

        float a0[4] = {0,0,0,0}, a1[4] = {0,0,0,0};
#pragma unroll
        for (int i = 0; i < 64; i += 4) {
            float xj[4][4];
#pragma unroll
            for (int j = 0; j < 4; j++) {
                float4 t = *(const float4*)&myS[j * 64 + i];
                xj[j][0] = t.x; xj[j][1] = t.y; xj[j][2] = t.z; xj[j][3] = t.w;
            }
#pragma unroll
            for (int s = 0; s < 4; s++) {
                float2 w = *(const float2*)&sWg[(i + s) * 64 + 2 * lane];
#pragma unroll
                for (int j = 0; j < 4; j++) {
                    a0[j] = fmaf(xj[j][s], w.x, a0[j]);
                    a1[j] = fmaf(xj[j][s], w.y, a1[j]);
                }
            }
        }
        __syncwarp();

        float t[4];
#pragma unroll
        for (int j = 0; j < 4; j++) t[j] = a0[j] + a1[j];
#pragma unroll
        for (int o = 16; o; o >>= 1)
#pragma unroll
            for (int j = 0; j < 4; j++) t[j] += __shfl_xor_sync(~0u, t[j], o);
        float q0[4], q1[4], vr[4];
#pragma unroll
        for (int j = 0; j < 4; j++) {
            float mu = t[j] * (1.f / 64.f);
            a0[j] -= mu; a1[j] -= mu;
            vr[j] = a0[j] * a0[j] + a1[j] * a1[j];
        }
#pragma unroll
        for (int o = 16; o; o >>= 1)
#pragma unroll
            for (int j = 0; j < 4; j++) vr[j] += __shfl_xor_sync(~0u, vr[j], o);
#pragma unroll
        for (int j = 0; j < 4; j++) {
            float rs = rsqrtf(vr[j] * (1.f / 64.f) + 1e-5f);
            q0[j] = fmaxf(fmaf(a0[j] * rs, gm.x, bt.x), 0.f);
            q1[j] = fmaxf(fmaf(a1[j] * rs, gm.y, bt.y), 0.f);
        }

        float bd[4];
#pragma unroll
        for (int j = 0; j < 4; j++) bd[j] = q0[j] * wb.x + q1[j] * wb.y;
#pragma unroll
        for (int o = 16; o; o >>= 1)
#pragma unroll
            for (int j = 0; j < 4; j++) bd[j] += __shfl_xor_sync(~0u, bd[j], o);
        if (lane == 0) {
#pragma unroll
            for (int j = 0; j < 4; j++)
                out[(size_t)13 * MPTS + p4 + j] = bd[j] + bb0;
        }

#pragma unroll
        for (int j = 0; j < 4; j++)
            *(float2*)&myS[j * 64 + 2 * lane] = make_float2(q0[j], q1[j]);
        __syncwarp();

        float u0[4] = {0,0,0,0}, u1[4] = {0,0,0,0};
        float v0[4] = {0,0,0,0}, v1[4] = {0,0,0,0};
#pragma unroll
        for (int i = 0; i < 64; i += 4) {
            float xj[4][4];
#pragma unroll
            for (int j = 0; j < 4; j++) {
                float4 tt = *(const float4*)&myS[j * 64 + i];
                xj[j][0] = tt.x; xj[j][1] = tt.y; xj[j][2] = tt.z; xj[j][3] = tt.w;
            }
#pragma unroll
            for (int s = 0; s < 4; s++) {
                float2 wq = *(const float2*)&sWq[(i + s) * 64 + 2 * lane];
                float2 wk = *(const float2*)&sWk[(i + s) * 64 + 2 * lane];
#pragma unroll
                for (int j = 0; j < 4; j++) {
                    u0[j] = fmaf(xj[j][s], wq.x, u0[j]);
                    u1[j] = fmaf(xj[j][s], wq.y, u1[j]);
                    v0[j] = fmaf(xj[j][s], wk.x, v0[j]);
                    v1[j] = fmaf(xj[j][s], wk.y, v1[j]);
                }
            }
        }
        __syncwarp();
#pragma unroll
        for (int j = 0; j < 4; j++) {
            size_t o = (size_t)(p4 + j) * 64 + 2 * lane;
            *(float2*)&g_Qp[o] = make_float2(u0[j], u1[j]);
            *(float2*)&g_Kb[o] = make_float2(v0[j], v1[j]);
        }
    }
}

// ---------------------------------------------------------------------------
// Kernel A2: 4 points/warp.  Vo = sem @ W_vo   (96 -> 64, single GEMV)
// ---------------------------------------------------------------------------
__global__ void __launch_bounds__(256) kA2(const float* __restrict__ sem)
{
    extern __shared__ float sm[];
    float* sW = sm;             // 6144
    float* stage = sm + 6144;   // 8 warps * 384

    for (int i = threadIdx.x; i < 6144; i += 256) sW[i] = g_Wvo[i];
    __syncthreads();

    const int lane = threadIdx.x & 31;
    float* myS = stage + (threadIdx.x >> 5) * 384;
    const int warp = (blockIdx.x * blockDim.x + threadIdx.x) >> 5;
    const int nw   = (gridDim.x * blockDim.x) >> 5;

    for (int p4 = warp * 4; p4 < MPTS; p4 += nw * 4) {
        {
            const float4* ssrc = (const float4*)(sem + (size_t)p4 * 96);
            float4* sdst = (float4*)myS;
            sdst[lane]      = ssrc[lane];
            sdst[lane + 32] = ssrc[lane + 32];
            sdst[lane + 64] = ssrc[lane + 64];
        }
        __syncwarp();

        float o0[4] = {0,0,0,0}, o1[4] = {0,0,0,0};
#pragma unroll
        for (int i = 0; i < 96; i += 4) {
            float xj[4][4];
#pragma unroll
            for (int j = 0; j < 4; j++) {
                float4 t = *(const float4*)&myS[j * 96 + i];
                xj[j][0] = t.x; xj[j][1] = t.y; xj[j][2] = t.z; xj[j][3] = t.w;
            }
#pragma unroll
            for (int s = 0; s < 4; s++) {
                float2 w = *(const float2*)&sW[(i + s) * 64 + 2 * lane];
#pragma unroll
                for (int j = 0; j < 4; j++) {
                    o0[j] = fmaf(xj[j][s], w.x, o0[j]);
                    o1[j] = fmaf(xj[j][s], w.y, o1[j]);
                }
            }
        }
        __syncwarp();
#pragma unroll
        for (int j = 0; j < 4; j++)
            *(float2*)&g_Vo[(size_t)(p4 + j) * 64 + 2 * lane] = make_float2(o0[j], o1[j]);
    }
}

// ---------------------------------------------------------------------------
// Kernel B: attention, 1 point/warp, smem-transpose logit reduction.
//   phase1: lanes compute coalesced partials for each k -> sPart[k*36+lane]
//   phase2: lane k sums its contiguous row (8x LDS.128) -> logit in lane k
// __launch_bounds__(256,5): 5 blocks/SM -> 40 warps (occ 62.5%).
// Block smem: sPe 6.9KB + sBo 0.25KB + sPart 32.3KB = 39.5KB; 5x = 197KB < 228KB.
// ---------------------------------------------------------------------------
__global__ void __launch_bounds__(256, 5) kB(
    const int* __restrict__ coords, const int* __restrict__ nbr,
    const float* __restrict__ pe, const float* __restrict__ bo,
    float* __restrict__ out)
{
    __shared__ float sPe[KN * 64];
    __shared__ float sBo[64];
    __shared__ float sPart[8][28 * 36];   // per-warp 28 rows x 36 stride (16B-aligned rows)

    for (int i = threadIdx.x; i < KN * 64; i += 256) sPe[i] = pe[i];
    if (threadIdx.x < 64) sBo[threadIdx.x] = bo[threadIdx.x];
    __syncthreads();

    const int lane = threadIdx.x & 31;
    float* part = sPart[threadIdx.x >> 5];
    const int warp = (blockIdx.x * blockDim.x + threadIdx.x) >> 5;
    const int nw   = (gridDim.x * blockDim.x) >> 5;
    const float2 bo2 = *(const float2*)&sBo[2 * lane];

    const size_t off_aff = (size_t)14 * MPTS;
    const size_t off_ref = (size_t)41 * MPTS;
    const size_t off_nbr = (size_t)105 * MPTS;
    const size_t off_msk = (size_t)132 * MPTS;

    for (int p = warp; p < MPTS; p += nw) {
        const unsigned lrow = 2u * lane;
        float2 q = *(const float2*)&g_Qp[((unsigned)p << 6) + lrow];

        int cx = coords[3 * p], cy = coords[3 * p + 1], cz = coords[3 * p + 2];

        // pack = idx | pos<<17 | valid<<22  (idx < 2^17)
        int packed = 0;
        if (lane < KN) {
            int idx = nbr[(size_t)p * KN + lane];
            int rx = coords[3 * idx] - cx, ry = coords[3 * idx + 1] - cy,
                rz = coords[3 * idx + 2] - cz;
            int vld = (max(abs(rx), max(abs(ry), abs(rz))) <= 1);
            int pos = min(max(rx + 1, 0), 2) * 9 + min(max(ry + 1, 0), 2) * 3
                    + min(max(rz + 1, 0), 2);
            packed = idx | (pos << 17) | (vld << 22);
        }

        // phase 1: coalesced partials
#pragma unroll
        for (int k = 0; k < KN; k++) {
            int pk = __shfl_sync(~0u, packed, k);
            unsigned idx = (unsigned)(pk & 0x1FFFF);
            unsigned pos = (unsigned)(pk >> 17) & 31u;
            float2 kb = *(const float2*)&g_Kb[(idx << 6) + lrow];
            float2 pr = *(const float2*)&sPe[(pos << 6) + lrow];
            part[k * 36 + lane] = q.x * (kb.x + pr.x) + q.y * (kb.y + pr.y);
        }
        __syncwarp();

        // phase 2: lane k sums its row
        float logit = -1e30f;
        if (lane < KN) {
            const float* rw = part + lane * 36;
            float4 t0 = *(const float4*)(rw +  0);
            float4 t1 = *(const float4*)(rw +  4);
            float4 t2 = *(const float4*)(rw +  8);
            float4 t3 = *(const float4*)(rw + 12);
            float4 t4 = *(const float4*)(rw + 16);
            float4 t5 = *(const float4*)(rw + 20);
            float4 t6 = *(const float4*)(rw + 24);
            float4 t7 = *(const float4*)(rw + 28);
            float s01 = (t0.x + t0.y) + (t0.z + t0.w) + (t1.x + t1.y) + (t1.z + t1.w);
            float s23 = (t2.x + t2.y) + (t2.z + t2.w) + (t3.x + t3.y) + (t3.z + t3.w);
            float s45 = (t4.x + t4.y) + (t4.z + t4.w) + (t5.x + t5.y) + (t5.z + t5.w);
            float s67 = (t6.x + t6.y) + (t6.z + t6.w) + (t7.x + t7.y) + (t7.z + t7.w);
            float s = (s01 + s23) + (s45 + s67);
            logit = (packed >> 22) ? s * 0.125f : -10000.0f;
        }
        __syncwarp();

        // softmax over warp (lanes >= 27 -> exp underflow to 0)
        float mx = logit;
#pragma unroll
        for (int o = 16; o; o >>= 1)
            mx = fmaxf(mx, __shfl_xor_sync(~0u, mx, o));
        float e = __expf(logit - mx);
        float ssum = e;
#pragma unroll
        for (int o = 16; o; o >>= 1)
            ssum += __shfl_xor_sync(~0u, ssum, o);
        float aff = e / ssum;

        // aggregate Vo (two accumulators for chain ILP)
        float2 r = *(const float2*)&g_Vo[((unsigned)p << 6) + lrow];
        float2 r2 = make_float2(0.f, 0.f);
#pragma unroll
        for (int k = 0; k < KN; k += 2) {
            float aa = __shfl_sync(~0u, aff, k);
            int   pk = __shfl_sync(~0u, packed, k);
            float2 v = *(const float2*)&g_Vo[(((unsigned)pk & 0x1FFFFu) << 6) + lrow];
            r.x = fmaf(aa, v.x, r.x); r.y = fmaf(aa, v.y, r.y);
            if (k + 1 < KN) {
                float ab = __shfl_sync(~0u, aff, k + 1);
                int   pb = __shfl_sync(~0u, packed, k + 1);
                float2 w = *(const float2*)&g_Vo[(((unsigned)pb & 0x1FFFFu) << 6) + lrow];
                r2.x = fmaf(ab, w.x, r2.x); r2.y = fmaf(ab, w.y, r2.y);
            }
        }
        r.x += r2.x; r.y += r2.y;

        *(float2*)&out[off_ref + ((size_t)p << 6) + lrow] =
            make_float2(r.x + bo2.x, r.y + bo2.y);
        if (lane < KN) {
            size_t a = (size_t)p * KN + lane;
            out[off_aff + a] = aff;
            out[off_nbr + a] = (float)(packed & 0x1FFFF);
            out[off_msk + a] = (packed >> 22) ? 1.f : 0.f;
        }
    }
}

// ---------------------------------------------------------------------------
// Kernel C: logits = refined_feat @ Wc + bc  (reads refined from out buffer)
// ---------------------------------------------------------------------------
__global__ void __launch_bounds__(256) kC(
    const float* __restrict__ Wc, const float* __restrict__ bc,
    float* __restrict__ out)
{
    __shared__ float sWc[832];
    __shared__ float sBc[16];
    __shared__ float stage[8 * 256];
    for (int i = threadIdx.x; i < 832; i += 256) sWc[i] = Wc[i];
    if (threadIdx.x < 16) sBc[threadIdx.x] = (threadIdx.x < 13) ? bc[threadIdx.x] : 0.f;
    __syncthreads();

    const int lane = threadIdx.x & 31;
    float* myS = stage + (threadIdx.x >> 5) * 256;
    const int warp = (blockIdx.x * blockDim.x + threadIdx.x) >> 5;
    const int nw   = (gridDim.x * blockDim.x) >> 5;
    const float* refv = out + (size_t)41 * MPTS;

    for (int p4 = warp * 4; p4 < MPTS; p4 += nw * 4) {
        {
            const float4* rs = (const float4*)(refv + (size_t)p4 * 64);
            float4* sdst = (float4*)myS;
            sdst[lane]      = rs[lane];
            sdst[lane + 32] = rs[lane + 32];
        }
        __syncwarp();

        float c[4];
#pragma unroll
        for (int j = 0; j < 4; j++) c[j] = (lane < 13) ? sBc[lane] : 0.f;
#pragma unroll
        for (int i = 0; i < 64; i += 4) {
            float xj[4][4];
#pragma unroll
            for (int j = 0; j < 4; j++) {
                float4 t = *(const float4*)&myS[j * 64 + i];
                xj[j][0] = t.x; xj[j][1] = t.y; xj[j][2] = t.z; xj[j][3] = t.w;
            }
#pragma unroll
            for (int s = 0; s < 4; s++) {
                float w = (lane < 13) ? sWc[(i + s) * 13 + lane] : 0.f;
#pragma unroll
                for (int j = 0; j < 4; j++) c[j] = fmaf(xj[j][s], w, c[j]);
            }
        }
        __syncwarp();
        if (lane < 13) {
#pragma unroll
            for (int j = 0; j < 4; j++)
                out[(size_t)(p4 + j) * 13 + lane] = c[j];
        }
    }
}

extern "C" void kernel_launch(void* const* d_in, const int* in_sizes, int n_in,
                              void* d_out, int out_size)
{
    const float* geo    = (const float*)d_in[0];
    const float* sem    = (const float*)d_in[1];
    const int*   coords = (const int*)d_in[2];
    const int*   nbr    = (const int*)d_in[3];   // int32 (JAX x64 off)
    const float* Wg     = (const float*)d_in[4];
    const float* gam    = (const float*)d_in[5];
    const float* bet    = (const float*)d_in[6];
    const float* Wb     = (const float*)d_in[7];
    const float* bb     = (const float*)d_in[8];
    const float* Wq     = (const float*)d_in[9];
    const float* Wk     = (const float*)d_in[10];
    const float* Wv     = (const float*)d_in[11];
    const float* pe     = (const float*)d_in[12];
    const float* Wo     = (const float*)d_in[13];
    const float* bo     = (const float*)d_in[14];
    const float* Wc     = (const float*)d_in[15];
    const float* bc     = (const float*)d_in[16];
    float* out = (float*)d_out;

    const int smemA1 = 14528 * 4;   // 58112 B
    const int smemA2 = 9216 * 4;    // 36864 B
    cudaFuncSetAttribute(kA1, cudaFuncAttributeMaxDynamicSharedMemorySize, smemA1);

    kW<<<24, 256>>>(Wv, Wo);
    kA1<<<592, 256, smemA1>>>(geo, Wg, gam, bet, Wb, bb, Wq, Wk, out);
    kA2<<<592, 256, smemA2>>>(sem);
    kB<<<12500, 256>>>(coords, nbr, pe, bo, out);
    kC<<<592, 256>>>(Wc, bc, out);
}

// round 11
// speedup vs baseline: 1.1015x; 1.1015x over previous
#include <cuda_runtime.h>

#define MPTS 100000
#define KN   27

// Scratch (__device__ globals)
__device__ float g_Qp[MPTS * 64];
__device__ float g_Kb[MPTS * 64];
__device__ float g_Vo[MPTS * 64];
__device__ float g_QPE[MPTS * 32];
__device__ float g_Wvo[96 * 64];
__device__ float g_Wqpe[64 * 32];

// ---------------------------------------------------------------------------
// Kernel W: fold W_vo = Wv@Wo [96,64]  and  Wqpe[i][pos] = sum_j Wq[i][j]*pe[pos][j]
// ---------------------------------------------------------------------------
__global__ void kW(const float* __restrict__ Wv, const float* __restrict__ Wo,
                   const float* __restrict__ Wq, const float* __restrict__ pe)
{
    int t = blockIdx.x * 256 + threadIdx.x;
    if (t < 96 * 64) {
        int row = t >> 6, col = t & 63;
        float s = 0.f;
#pragma unroll 16
        for (int i = 0; i < 64; i++)
            s = fmaf(Wv[row * 64 + i], Wo[i * 64 + col], s);
        g_Wvo[t] = s;
    } else if (t < 96 * 64 + 64 * 32) {
        int u = t - 96 * 64;
        int i = u >> 5, pos = u & 31;
        float s = 0.f;
        if (pos < KN) {
#pragma unroll 16
            for (int j = 0; j < 64; j++)
                s = fmaf(Wq[i * 64 + j], pe[pos * 64 + j], s);
        }
        g_Wqpe[u] = s;
    }
}

// ---------------------------------------------------------------------------
// Kernel A1: 4 points/warp.  a = geo@Wg -> LN -> relu -> q
//   bdy = q@Wb+bb ; Qp = q@Wq ; Kb = q@Wk ; QPE = q@Wqpe (27 pos dots)
// ---------------------------------------------------------------------------
__global__ void __launch_bounds__(256) kA1(
    const float* __restrict__ geo, const float* __restrict__ Wg,
    const float* __restrict__ gam, const float* __restrict__ bet,
    const float* __restrict__ Wb, const float* __restrict__ bb,
    const float* __restrict__ Wq, const float* __restrict__ Wk,
    float* __restrict__ out)
{
    extern __shared__ float sm[];
    float* sWg = sm;            // 4096
    float* sWq = sm + 4096;     // 4096
    float* sWk = sm + 8192;     // 4096
    float* sWqpe = sm + 12288;  // 2048
    float* sGm = sm + 14336;    // 64
    float* sBt = sm + 14400;    // 64
    float* sWb = sm + 14464;    // 64
    float* stage = sm + 14528;  // 8 warps * 256

    for (int i = threadIdx.x; i < 4096; i += 256) {
        sWg[i] = Wg[i]; sWq[i] = Wq[i]; sWk[i] = Wk[i];
    }
    for (int i = threadIdx.x; i < 2048; i += 256) sWqpe[i] = g_Wqpe[i];
    if (threadIdx.x < 64) {
        sGm[threadIdx.x] = gam[threadIdx.x];
        sBt[threadIdx.x] = bet[threadIdx.x];
        sWb[threadIdx.x] = Wb[threadIdx.x];
    }
    __syncthreads();

    const int lane = threadIdx.x & 31;
    float* myS = stage + (threadIdx.x >> 5) * 256;
    const int warp = (blockIdx.x * blockDim.x + threadIdx.x) >> 5;
    const int nw   = (gridDim.x * blockDim.x) >> 5;
    const float bb0 = bb[0];
    const float2 gm = *(const float2*)&sGm[2 * lane];
    const float2 bt = *(const float2*)&sBt[2 * lane];
    const float2 wb = *(const float2*)&sWb[2 * lane];

    for (int p4 = warp * 4; p4 < MPTS; p4 += nw * 4) {
        {
            const float4* gsrc = (const float4*)(geo + (size_t)p4 * 64);
            float4* sdst = (float4*)myS;
            sdst[lane]      = gsrc[lane];
            sdst[lane + 32] = gsrc[lane + 32];
        }
        __syncwarp();

        float a0[4] = {0,0,0,0}, a1[4] = {0,0,0,0};
#pragma unroll
        for (int i = 0; i < 64; i += 4) {
            float xj[4][4];
#pragma unroll
            for (int j = 0; j < 4; j++) {
                float4 t = *(const float4*)&myS[j * 64 + i];
                xj[j][0] = t.x; xj[j][1] = t.y; xj[j][2] = t.z; xj[j][3] = t.w;
            }
#pragma unroll
            for (int s = 0; s < 4; s++) {
                float2 w = *(const float2*)&sWg[(i + s) * 64 + 2 * lane];
#pragma unroll
                for (int j = 0; j < 4; j++) {
                    a0[j] = fmaf(xj[j][s], w.x, a0[j]);
                    a1[j] = fmaf(xj[j][s], w.y, a1[j]);
                }
            }
        }
        __syncwarp();

        float t[4];
#pragma unroll
        for (int j = 0; j < 4; j++) t[j] = a0[j] + a1[j];
#pragma unroll
        for (int o = 16; o; o >>= 1)
#pragma unroll
            for (int j = 0; j < 4; j++) t[j] += __shfl_xor_sync(~0u, t[j], o);
        float q0[4], q1[4], vr[4];
#pragma unroll
        for (int j = 0; j < 4; j++) {
            float mu = t[j] * (1.f / 64.f);
            a0[j] -= mu; a1[j] -= mu;
            vr[j] = a0[j] * a0[j] + a1[j] * a1[j];
        }
#pragma unroll
        for (int o = 16; o; o >>= 1)
#pragma unroll
            for (int j = 0; j < 4; j++) vr[j] += __shfl_xor_sync(~0u, vr[j], o);
#pragma unroll
        for (int j = 0; j < 4; j++) {
            float rs = rsqrtf(vr[j] * (1.f / 64.f) + 1e-5f);
            q0[j] = fmaxf(fmaf(a0[j] * rs, gm.x, bt.x), 0.f);
            q1[j] = fmaxf(fmaf(a1[j] * rs, gm.y, bt.y), 0.f);
        }

        float bd[4];
#pragma unroll
        for (int j = 0; j < 4; j++) bd[j] = q0[j] * wb.x + q1[j] * wb.y;
#pragma unroll
        for (int o = 16; o; o >>= 1)
#pragma unroll
            for (int j = 0; j < 4; j++) bd[j] += __shfl_xor_sync(~0u, bd[j], o);
        if (lane == 0) {
#pragma unroll
            for (int j = 0; j < 4; j++)
                out[(size_t)13 * MPTS + p4 + j] = bd[j] + bb0;
        }

#pragma unroll
        for (int j = 0; j < 4; j++)
            *(float2*)&myS[j * 64 + 2 * lane] = make_float2(q0[j], q1[j]);
        __syncwarp();

        float u0[4] = {0,0,0,0}, u1[4] = {0,0,0,0};
        float v0[4] = {0,0,0,0}, v1[4] = {0,0,0,0};
        float c[4]  = {0,0,0,0};
#pragma unroll
        for (int i = 0; i < 64; i += 4) {
            float xj[4][4];
#pragma unroll
            for (int j = 0; j < 4; j++) {
                float4 tt = *(const float4*)&myS[j * 64 + i];
                xj[j][0] = tt.x; xj[j][1] = tt.y; xj[j][2] = tt.z; xj[j][3] = tt.w;
            }
#pragma unroll
            for (int s = 0; s < 4; s++) {
                float2 wq = *(const float2*)&sWq[(i + s) * 64 + 2 * lane];
                float2 wk = *(const float2*)&sWk[(i + s) * 64 + 2 * lane];
                float wpe = sWqpe[(i + s) * 32 + lane];
#pragma unroll
                for (int j = 0; j < 4; j++) {
                    u0[j] = fmaf(xj[j][s], wq.x, u0[j]);
                    u1[j] = fmaf(xj[j][s], wq.y, u1[j]);
                    v0[j] = fmaf(xj[j][s], wk.x, v0[j]);
                    v1[j] = fmaf(xj[j][s], wk.y, v1[j]);
                    c[j]  = fmaf(xj[j][s], wpe, c[j]);
                }
            }
        }
        __syncwarp();
#pragma unroll
        for (int j = 0; j < 4; j++) {
            size_t o = (size_t)(p4 + j) * 64 + 2 * lane;
            *(float2*)&g_Qp[o] = make_float2(u0[j], u1[j]);
            *(float2*)&g_Kb[o] = make_float2(v0[j], v1[j]);
            g_QPE[(size_t)(p4 + j) * 32 + lane] = c[j];
        }
    }
}

// ---------------------------------------------------------------------------
// Kernel A2: 4 points/warp.  Vo = sem @ W_vo   (96 -> 64, single GEMV)
// ---------------------------------------------------------------------------
__global__ void __launch_bounds__(256) kA2(const float* __restrict__ sem)
{
    extern __shared__ float sm[];
    float* sW = sm;             // 6144
    float* stage = sm + 6144;   // 8 warps * 384

    for (int i = threadIdx.x; i < 6144; i += 256) sW[i] = g_Wvo[i];
    __syncthreads();

    const int lane = threadIdx.x & 31;
    float* myS = stage + (threadIdx.x >> 5) * 384;
    const int warp = (blockIdx.x * blockDim.x + threadIdx.x) >> 5;
    const int nw   = (gridDim.x * blockDim.x) >> 5;

    for (int p4 = warp * 4; p4 < MPTS; p4 += nw * 4) {
        {
            const float4* ssrc = (const float4*)(sem + (size_t)p4 * 96);
            float4* sdst = (float4*)myS;
            sdst[lane]      = ssrc[lane];
            sdst[lane + 32] = ssrc[lane + 32];
            sdst[lane + 64] = ssrc[lane + 64];
        }
        __syncwarp();

        float o0[4] = {0,0,0,0}, o1[4] = {0,0,0,0};
#pragma unroll
        for (int i = 0; i < 96; i += 4) {
            float xj[4][4];
#pragma unroll
            for (int j = 0; j < 4; j++) {
                float4 t = *(const float4*)&myS[j * 96 + i];
                xj[j][0] = t.x; xj[j][1] = t.y; xj[j][2] = t.z; xj[j][3] = t.w;
            }
#pragma unroll
            for (int s = 0; s < 4; s++) {
                float2 w = *(const float2*)&sW[(i + s) * 64 + 2 * lane];
#pragma unroll
                for (int j = 0; j < 4; j++) {
                    o0[j] = fmaf(xj[j][s], w.x, o0[j]);
                    o1[j] = fmaf(xj[j][s], w.y, o1[j]);
                }
            }
        }
        __syncwarp();
#pragma unroll
        for (int j = 0; j < 4; j++)
            *(float2*)&g_Vo[(size_t)(p4 + j) * 64 + 2 * lane] = make_float2(o0[j], o1[j]);
    }
}

// ---------------------------------------------------------------------------
// Kernel B: attention, 1 point/warp, smem-transpose logit reduction.
// pe-term precomputed (g_QPE): phase1 is pure Kb gather dot.
// ---------------------------------------------------------------------------
__global__ void __launch_bounds__(256, 5) kB(
    const int* __restrict__ coords, const int* __restrict__ nbr,
    const float* __restrict__ bo, float* __restrict__ out)
{
    __shared__ float sBo[64];
    __shared__ float sPart[8][28 * 36];   // per-warp 28 rows x 36 stride

    if (threadIdx.x < 64) sBo[threadIdx.x] = bo[threadIdx.x];
    __syncthreads();

    const int lane = threadIdx.x & 31;
    float* part = sPart[threadIdx.x >> 5];
    const int warp = (blockIdx.x * blockDim.x + threadIdx.x) >> 5;
    const int nw   = (gridDim.x * blockDim.x) >> 5;
    const float2 bo2 = *(const float2*)&sBo[2 * lane];

    const size_t off_aff = (size_t)14 * MPTS;
    const size_t off_ref = (size_t)41 * MPTS;
    const size_t off_nbr = (size_t)105 * MPTS;
    const size_t off_msk = (size_t)132 * MPTS;

    for (int p = warp; p < MPTS; p += nw) {
        const unsigned lrow = 2u * lane;
        float2 q = *(const float2*)&g_Qp[((unsigned)p << 6) + lrow];
        float qpe_l = g_QPE[((unsigned)p << 5) + lane];   // element `lane` of QPE row

        int cx = coords[3 * p], cy = coords[3 * p + 1], cz = coords[3 * p + 2];

        // pack = idx | pos<<17 | valid<<22  (idx < 2^17)
        int packed = 0;
        if (lane < KN) {
            int idx = nbr[(size_t)p * KN + lane];
            int rx = coords[3 * idx] - cx, ry = coords[3 * idx + 1] - cy,
                rz = coords[3 * idx + 2] - cz;
            int vld = (max(abs(rx), max(abs(ry), abs(rz))) <= 1);
            int pos = min(max(rx + 1, 0), 2) * 9 + min(max(ry + 1, 0), 2) * 3
                    + min(max(rz + 1, 0), 2);
            packed = idx | (pos << 17) | (vld << 22);
        }

        // phase 1: coalesced partials (pure Kb gather dot)
#pragma unroll
        for (int k = 0; k < KN; k++) {
            int pk = __shfl_sync(~0u, packed, k);
            unsigned idx = (unsigned)(pk & 0x1FFFF);
            float2 kb = *(const float2*)&g_Kb[(idx << 6) + lrow];
            part[k * 36 + lane] = q.x * kb.x + q.y * kb.y;
        }
        __syncwarp();

        // pe term for my neighbor: QPE[pos_mine] via shuffle
        int mypos = (packed >> 17) & 31;
        float qpe_mine = __shfl_sync(~0u, qpe_l, mypos);

        // phase 2: lane k sums its row
        float logit = -1e30f;
        if (lane < KN) {
            const float* rw = part + lane * 36;
            float4 t0 = *(const float4*)(rw +  0);
            float4 t1 = *(const float4*)(rw +  4);
            float4 t2 = *(const float4*)(rw +  8);
            float4 t3 = *(const float4*)(rw + 12);
            float4 t4 = *(const float4*)(rw + 16);
            float4 t5 = *(const float4*)(rw + 20);
            float4 t6 = *(const float4*)(rw + 24);
            float4 t7 = *(const float4*)(rw + 28);
            float s01 = (t0.x + t0.y) + (t0.z + t0.w) + (t1.x + t1.y) + (t1.z + t1.w);
            float s23 = (t2.x + t2.y) + (t2.z + t2.w) + (t3.x + t3.y) + (t3.z + t3.w);
            float s45 = (t4.x + t4.y) + (t4.z + t4.w) + (t5.x + t5.y) + (t5.z + t5.w);
            float s67 = (t6.x + t6.y) + (t6.z + t6.w) + (t7.x + t7.y) + (t7.z + t7.w);
            float s = (s01 + s23) + (s45 + s67) + qpe_mine;
            logit = (packed >> 22) ? s * 0.125f : -10000.0f;
        }
        __syncwarp();

        // softmax over warp (lanes >= 27 -> exp underflow to 0)
        float mx = logit;
#pragma unroll
        for (int o = 16; o; o >>= 1)
            mx = fmaxf(mx, __shfl_xor_sync(~0u, mx, o));
        float e = __expf(logit - mx);
        float ssum = e;
#pragma unroll
        for (int o = 16; o; o >>= 1)
            ssum += __shfl_xor_sync(~0u, ssum, o);
        float aff = e / ssum;

        // aggregate Vo (two accumulators for chain ILP)
        float2 r = *(const float2*)&g_Vo[((unsigned)p << 6) + lrow];
        float2 r2 = make_float2(0.f, 0.f);
#pragma unroll
        for (int k = 0; k < KN; k += 2) {
            float aa = __shfl_sync(~0u, aff, k);
            int   pk = __shfl_sync(~0u, packed, k);
            float2 v = *(const float2*)&g_Vo[(((unsigned)pk & 0x1FFFFu) << 6) + lrow];
            r.x = fmaf(aa, v.x, r.x); r.y = fmaf(aa, v.y, r.y);
            if (k + 1 < KN) {
                float ab = __shfl_sync(~0u, aff, k + 1);
                int   pb = __shfl_sync(~0u, packed, k + 1);
                float2 w = *(const float2*)&g_Vo[(((unsigned)pb & 0x1FFFFu) << 6) + lrow];
                r2.x = fmaf(ab, w.x, r2.x); r2.y = fmaf(ab, w.y, r2.y);
            }
        }
        r.x += r2.x; r.y += r2.y;

        *(float2*)&out[off_ref + ((size_t)p << 6) + lrow] =
            make_float2(r.x + bo2.x, r.y + bo2.y);
        if (lane < KN) {
            size_t a = (size_t)p * KN + lane;
            out[off_aff + a] = aff;
            out[off_nbr + a] = (float)(packed & 0x1FFFF);
            out[off_msk + a] = (packed >> 22) ? 1.f : 0.f;
        }
    }
}

// ---------------------------------------------------------------------------
// Kernel C: logits = refined_feat @ Wc + bc  (reads refined from out buffer)
// ---------------------------------------------------------------------------
__global__ void __launch_bounds__(256) kC(
    const float* __restrict__ Wc, const float* __restrict__ bc,
    float* __restrict__ out)
{
    __shared__ float sWc[832];
    __shared__ float sBc[16];
    __shared__ float stage[8 * 256];
    for (int i = threadIdx.x; i < 832; i += 256) sWc[i] = Wc[i];
    if (threadIdx.x < 16) sBc[threadIdx.x] = (threadIdx.x < 13) ? bc[threadIdx.x] : 0.f;
    __syncthreads();

    const int lane = threadIdx.x & 31;
    float* myS = stage + (threadIdx.x >> 5) * 256;
    const int warp = (blockIdx.x * blockDim.x + threadIdx.x) >> 5;
    const int nw   = (gridDim.x * blockDim.x) >> 5;
    const float* refv = out + (size_t)41 * MPTS;

    for (int p4 = warp * 4; p4 < MPTS; p4 += nw * 4) {
        {
            const float4* rs = (const float4*)(refv + (size_t)p4 * 64);
            float4* sdst = (float4*)myS;
            sdst[lane]      = rs[lane];
            sdst[lane + 32] = rs[lane + 32];
        }
        __syncwarp();

        float c[4];
#pragma unroll
        for (int j = 0; j < 4; j++) c[j] = (lane < 13) ? sBc[lane] : 0.f;
#pragma unroll
        for (int i = 0; i < 64; i += 4) {
            float xj[4][4];
#pragma unroll
            for (int j = 0; j < 4; j++) {
                float4 t = *(const float4*)&myS[j * 64 + i];
                xj[j][0] = t.x; xj[j][1] = t.y; xj[j][2] = t.z; xj[j][3] = t.w;
            }
#pragma unroll
            for (int s = 0; s < 4; s++) {
                float w = (lane < 13) ? sWc[(i + s) * 13 + lane] : 0.f;
#pragma unroll
                for (int j = 0; j < 4; j++) c[j] = fmaf(xj[j][s], w, c[j]);
            }
        }
        __syncwarp();
        if (lane < 13) {
#pragma unroll
            for (int j = 0; j < 4; j++)
                out[(size_t)(p4 + j) * 13 + lane] = c[j];
        }
    }
}

extern "C" void kernel_launch(void* const* d_in, const int* in_sizes, int n_in,
                              void* d_out, int out_size)
{
    const float* geo    = (const float*)d_in[0];
    const float* sem    = (const float*)d_in[1];
    const int*   coords = (const int*)d_in[2];
    const int*   nbr    = (const int*)d_in[3];   // int32 (JAX x64 off)
    const float* Wg     = (const float*)d_in[4];
    const float* gam    = (const float*)d_in[5];
    const float* bet    = (const float*)d_in[6];
    const float* Wb     = (const float*)d_in[7];
    const float* bb     = (const float*)d_in[8];
    const float* Wq     = (const float*)d_in[9];
    const float* Wk     = (const float*)d_in[10];
    const float* Wv     = (const float*)d_in[11];
    const float* pe     = (const float*)d_in[12];
    const float* Wo     = (const float*)d_in[13];
    const float* bo     = (const float*)d_in[14];
    const float* Wc     = (const float*)d_in[15];
    const float* bc     = (const float*)d_in[16];
    float* out = (float*)d_out;

    const int smemA1 = 16576 * 4;   // 66304 B
    const int smemA2 = 9216 * 4;    // 36864 B
    cudaFuncSetAttribute(kA1, cudaFuncAttributeMaxDynamicSharedMemorySize, smemA1);

    kW<<<32, 256>>>(Wv, Wo, Wq, pe);
    kA1<<<592, 256, smemA1>>>(geo, Wg, gam, bet, Wb, bb, Wq, Wk, out);
    kA2<<<592, 256, smemA2>>>(sem);
    kB<<<12500, 256>>>(coords, nbr, bo, out);
    kC<<<592, 256>>>(Wc, bc, out);
}

// round 12
// speedup vs baseline: 1.1156x; 1.0128x over previous
#include <cuda_runtime.h>

#define MPTS 100000
#define KN   27

// Scratch (__device__ globals)
__device__ float g_Qp[MPTS * 64];
__device__ float g_Kb[MPTS * 64];
__device__ float g_Vo[MPTS * 64];
__device__ float g_QPE[MPTS * 32];
__device__ int   g_cpack[MPTS];
__device__ float g_Wvo[96 * 64];
__device__ float g_Wqpe[64 * 32];

// ---------------------------------------------------------------------------
// Kernel W: fold W_vo = Wv@Wo [96,64], Wqpe[i][pos] = Wq[i,:]·pe[pos,:],
//           and pack coords into one int per point.
// ---------------------------------------------------------------------------
__global__ void kW(const float* __restrict__ Wv, const float* __restrict__ Wo,
                   const float* __restrict__ Wq, const float* __restrict__ pe,
                   const int* __restrict__ coords)
{
    int t = blockIdx.x * 256 + threadIdx.x;
    if (t < 96 * 64) {
        int row = t >> 6, col = t & 63;
        float s = 0.f;
#pragma unroll 16
        for (int i = 0; i < 64; i++)
            s = fmaf(Wv[row * 64 + i], Wo[i * 64 + col], s);
        g_Wvo[t] = s;
    } else if (t < 96 * 64 + 64 * 32) {
        int u = t - 96 * 64;
        int i = u >> 5, pos = u & 31;
        float s = 0.f;
        if (pos < KN) {
#pragma unroll 16
            for (int j = 0; j < 64; j++)
                s = fmaf(Wq[i * 64 + j], pe[pos * 64 + j], s);
        }
        g_Wqpe[u] = s;
    }
    // coords packing (grid-stride over all points)
    for (int p = t; p < MPTS; p += gridDim.x * 256) {
        int x = coords[3 * p], y = coords[3 * p + 1], z = coords[3 * p + 2];
        g_cpack[p] = x | (y << 8) | (z << 16);
    }
}

// ---------------------------------------------------------------------------
// Kernel A1: 4 points/warp.  a = geo@Wg -> LN -> relu -> q
//   bdy = q@Wb+bb ; Qp = q@Wq ; Kb = q@Wk ; QPE = q@Wqpe (27 pos dots)
// ---------------------------------------------------------------------------
__global__ void __launch_bounds__(256) kA1(
    const float* __restrict__ geo, const float* __restrict__ Wg,
    const float* __restrict__ gam, const float* __restrict__ bet,
    const float* __restrict__ Wb, const float* __restrict__ bb,
    const float* __restrict__ Wq, const float* __restrict__ Wk,
    float* __restrict__ out)
{
    extern __shared__ float sm[];
    float* sWg = sm;            // 4096
    float* sWq = sm + 4096;     // 4096
    float* sWk = sm + 8192;     // 4096
    float* sWqpe = sm + 12288;  // 2048
    float* sGm = sm + 14336;    // 64
    float* sBt = sm + 14400;    // 64
    float* sWb = sm + 14464;    // 64
    float* stage = sm + 14528;  // 8 warps * 256

    for (int i = threadIdx.x; i < 4096; i += 256) {
        sWg[i] = Wg[i]; sWq[i] = Wq[i]; sWk[i] = Wk[i];
    }
    for (int i = threadIdx.x; i < 2048; i += 256) sWqpe[i] = g_Wqpe[i];
    if (threadIdx.x < 64) {
        sGm[threadIdx.x] = gam[threadIdx.x];
        sBt[threadIdx.x] = bet[threadIdx.x];
        sWb[threadIdx.x] = Wb[threadIdx.x];
    }
    __syncthreads();

    const int lane = threadIdx.x & 31;
    float* myS = stage + (threadIdx.x >> 5) * 256;
    const int warp = (blockIdx.x * blockDim.x + threadIdx.x) >> 5;
    const int nw   = (gridDim.x * blockDim.x) >> 5;
    const float bb0 = bb[0];
    const float2 gm = *(const float2*)&sGm[2 * lane];
    const float2 bt = *(const float2*)&sBt[2 * lane];
    const float2 wb = *(const float2*)&sWb[2 * lane];

    for (int p4 = warp * 4; p4 < MPTS; p4 += nw * 4) {
        {
            const float4* gsrc = (const float4*)(geo + (size_t)p4 * 64);
            float4* sdst = (float4*)myS;
            sdst[lane]      = gsrc[lane];
            sdst[lane + 32] = gsrc[lane + 32];
        }
        __syncwarp();

        float a0[4] = {0,0,0,0}, a1[4] = {0,0,0,0};
#pragma unroll
        for (int i = 0; i < 64; i += 4) {
            float xj[4][4];
#pragma unroll
            for (int j = 0; j < 4; j++) {
                float4 t = *(const float4*)&myS[j * 64 + i];
                xj[j][0] = t.x; xj[j][1] = t.y; xj[j][2] = t.z; xj[j][3] = t.w;
            }
#pragma unroll
            for (int s = 0; s < 4; s++) {
                float2 w = *(const float2*)&sWg[(i + s) * 64 + 2 * lane];
#pragma unroll
                for (int j = 0; j < 4; j++) {
                    a0[j] = fmaf(xj[j][s], w.x, a0[j]);
                    a1[j] = fmaf(xj[j][s], w.y, a1[j]);
                }
            }
        }
        __syncwarp();

        float t[4];
#pragma unroll
        for (int j = 0; j < 4; j++) t[j] = a0[j] + a1[j];
#pragma unroll
        for (int o = 16; o; o >>= 1)
#pragma unroll
            for (int j = 0; j < 4; j++) t[j] += __shfl_xor_sync(~0u, t[j], o);
        float q0[4], q1[4], vr[4];
#pragma unroll
        for (int j = 0; j < 4; j++) {
            float mu = t[j] * (1.f / 64.f);
            a0[j] -= mu; a1[j] -= mu;
            vr[j] = a0[j] * a0[j] + a1[j] * a1[j];
        }
#pragma unroll
        for (int o = 16; o; o >>= 1)
#pragma unroll
            for (int j = 0; j < 4; j++) vr[j] += __shfl_xor_sync(~0u, vr[j], o);
#pragma unroll
        for (int j = 0; j < 4; j++) {
            float rs = rsqrtf(vr[j] * (1.f / 64.f) + 1e-5f);
            q0[j] = fmaxf(fmaf(a0[j] * rs, gm.x, bt.x), 0.f);
            q1[j] = fmaxf(fmaf(a1[j] * rs, gm.y, bt.y), 0.f);
        }

        float bd[4];
#pragma unroll
        for (int j = 0; j < 4; j++) bd[j] = q0[j] * wb.x + q1[j] * wb.y;
#pragma unroll
        for (int o = 16; o; o >>= 1)
#pragma unroll
            for (int j = 0; j < 4; j++) bd[j] += __shfl_xor_sync(~0u, bd[j], o);
        if (lane == 0) {
#pragma unroll
            for (int j = 0; j < 4; j++)
                out[(size_t)13 * MPTS + p4 + j] = bd[j] + bb0;
        }

#pragma unroll
        for (int j = 0; j < 4; j++)
            *(float2*)&myS[j * 64 + 2 * lane] = make_float2(q0[j], q1[j]);
        __syncwarp();

        float u0[4] = {0,0,0,0}, u1[4] = {0,0,0,0};
        float v0[4] = {0,0,0,0}, v1[4] = {0,0,0,0};
        float c[4]  = {0,0,0,0};
#pragma unroll
        for (int i = 0; i < 64; i += 4) {
            float xj[4][4];
#pragma unroll
            for (int j = 0; j < 4; j++) {
                float4 tt = *(const float4*)&myS[j * 64 + i];
                xj[j][0] = tt.x; xj[j][1] = tt.y; xj[j][2] = tt.z; xj[j][3] = tt.w;
            }
#pragma unroll
            for (int s = 0; s < 4; s++) {
                float2 wq = *(const float2*)&sWq[(i + s) * 64 + 2 * lane];
                float2 wk = *(const float2*)&sWk[(i + s) * 64 + 2 * lane];
                float wpe = sWqpe[(i + s) * 32 + lane];
#pragma unroll
                for (int j = 0; j < 4; j++) {
                    u0[j] = fmaf(xj[j][s], wq.x, u0[j]);
                    u1[j] = fmaf(xj[j][s], wq.y, u1[j]);
                    v0[j] = fmaf(xj[j][s], wk.x, v0[j]);
                    v1[j] = fmaf(xj[j][s], wk.y, v1[j]);
                    c[j]  = fmaf(xj[j][s], wpe, c[j]);
                }
            }
        }
        __syncwarp();
#pragma unroll
        for (int j = 0; j < 4; j++) {
            size_t o = (size_t)(p4 + j) * 64 + 2 * lane;
            *(float2*)&g_Qp[o] = make_float2(u0[j], u1[j]);
            *(float2*)&g_Kb[o] = make_float2(v0[j], v1[j]);
            g_QPE[(size_t)(p4 + j) * 32 + lane] = c[j];
        }
    }
}

// ---------------------------------------------------------------------------
// Kernel A2: 4 points/warp.  Vo = sem @ W_vo   (96 -> 64, single GEMV)
// ---------------------------------------------------------------------------
__global__ void __launch_bounds__(256) kA2(const float* __restrict__ sem)
{
    extern __shared__ float sm[];
    float* sW = sm;             // 6144
    float* stage = sm + 6144;   // 8 warps * 384

    for (int i = threadIdx.x; i < 6144; i += 256) sW[i] = g_Wvo[i];
    __syncthreads();

    const int lane = threadIdx.x & 31;
    float* myS = stage + (threadIdx.x >> 5) * 384;
    const int warp = (blockIdx.x * blockDim.x + threadIdx.x) >> 5;
    const int nw   = (gridDim.x * blockDim.x) >> 5;

    for (int p4 = warp * 4; p4 < MPTS; p4 += nw * 4) {
        {
            const float4* ssrc = (const float4*)(sem + (size_t)p4 * 96);
            float4* sdst = (float4*)myS;
            sdst[lane]      = ssrc[lane];
            sdst[lane + 32] = ssrc[lane + 32];
            sdst[lane + 64] = ssrc[lane + 64];
        }
        __syncwarp();

        float o0[4] = {0,0,0,0}, o1[4] = {0,0,0,0};
#pragma unroll
        for (int i = 0; i < 96; i += 4) {
            float xj[4][4];
#pragma unroll
            for (int j = 0; j < 4; j++) {
                float4 t = *(const float4*)&myS[j * 96 + i];
                xj[j][0] = t.x; xj[j][1] = t.y; xj[j][2] = t.z; xj[j][3] = t.w;
            }
#pragma unroll
            for (int s = 0; s < 4; s++) {
                float2 w = *(const float2*)&sW[(i + s) * 64 + 2 * lane];
#pragma unroll
                for (int j = 0; j < 4; j++) {
                    o0[j] = fmaf(xj[j][s], w.x, o0[j]);
                    o1[j] = fmaf(xj[j][s], w.y, o1[j]);
                }
            }
        }
        __syncwarp();
#pragma unroll
        for (int j = 0; j < 4; j++)
            *(float2*)&g_Vo[(size_t)(p4 + j) * 64 + 2 * lane] = make_float2(o0[j], o1[j]);
    }
}

// ---------------------------------------------------------------------------
// Kernel B: attention, 1 point/warp, smem-transpose logit reduction.
// coords packed (1 gather instead of 3); pe-term precomputed (g_QPE).
// ---------------------------------------------------------------------------
__global__ void __launch_bounds__(256, 5) kB(
    const int* __restrict__ nbr, const float* __restrict__ bo,
    float* __restrict__ out)
{
    __shared__ float sBo[64];
    __shared__ float sPart[8][28 * 36];   // per-warp 28 rows x 36 stride

    if (threadIdx.x < 64) sBo[threadIdx.x] = bo[threadIdx.x];
    __syncthreads();

    const int lane = threadIdx.x & 31;
    float* part = sPart[threadIdx.x >> 5];
    const int warp = (blockIdx.x * blockDim.x + threadIdx.x) >> 5;
    const int nw   = (gridDim.x * blockDim.x) >> 5;
    const float2 bo2 = *(const float2*)&sBo[2 * lane];

    const size_t off_aff = (size_t)14 * MPTS;
    const size_t off_ref = (size_t)41 * MPTS;
    const size_t off_nbr = (size_t)105 * MPTS;
    const size_t off_msk = (size_t)132 * MPTS;

    for (int p = warp; p < MPTS; p += nw) {
        const unsigned lrow = 2u * lane;
        float2 q = *(const float2*)&g_Qp[((unsigned)p << 6) + lrow];
        float qpe_l = g_QPE[((unsigned)p << 5) + lane];

        int cp = g_cpack[p];
        int cx = cp & 255, cy = (cp >> 8) & 255, cz = (cp >> 16) & 255;

        // pack = idx | pos<<17 | valid<<22  (idx < 2^17)
        int packed = 0;
        if (lane < KN) {
            int idx = nbr[(size_t)p * KN + lane];
            int np = g_cpack[idx];
            int rx = (np & 255) - cx;
            int ry = ((np >> 8) & 255) - cy;
            int rz = ((np >> 16) & 255) - cz;
            int vld = (max(abs(rx), max(abs(ry), abs(rz))) <= 1);
            int pos = min(max(rx + 1, 0), 2) * 9 + min(max(ry + 1, 0), 2) * 3
                    + min(max(rz + 1, 0), 2);
            packed = idx | (pos << 17) | (vld << 22);
        }

        // phase 1: coalesced partials (pure Kb gather dot)
#pragma unroll
        for (int k = 0; k < KN; k++) {
            int pk = __shfl_sync(~0u, packed, k);
            unsigned idx = (unsigned)(pk & 0x1FFFF);
            float2 kb = *(const float2*)&g_Kb[(idx << 6) + lrow];
            part[k * 36 + lane] = q.x * kb.x + q.y * kb.y;
        }
        __syncwarp();

        // pe term for my neighbor: QPE[pos_mine] via shuffle
        int mypos = (packed >> 17) & 31;
        float qpe_mine = __shfl_sync(~0u, qpe_l, mypos);

        // phase 2: lane k sums its row
        float logit = -1e30f;
        if (lane < KN) {
            const float* rw = part + lane * 36;
            float4 t0 = *(const float4*)(rw +  0);
            float4 t1 = *(const float4*)(rw +  4);
            float4 t2 = *(const float4*)(rw +  8);
            float4 t3 = *(const float4*)(rw + 12);
            float4 t4 = *(const float4*)(rw + 16);
            float4 t5 = *(const float4*)(rw + 20);
            float4 t6 = *(const float4*)(rw + 24);
            float4 t7 = *(const float4*)(rw + 28);
            float s01 = (t0.x + t0.y) + (t0.z + t0.w) + (t1.x + t1.y) + (t1.z + t1.w);
            float s23 = (t2.x + t2.y) + (t2.z + t2.w) + (t3.x + t3.y) + (t3.z + t3.w);
            float s45 = (t4.x + t4.y) + (t4.z + t4.w) + (t5.x + t5.y) + (t5.z + t5.w);
            float s67 = (t6.x + t6.y) + (t6.z + t6.w) + (t7.x + t7.y) + (t7.z + t7.w);
            float s = (s01 + s23) + (s45 + s67) + qpe_mine;
            logit = (packed >> 22) ? s * 0.125f : -10000.0f;
        }
        __syncwarp();

        // softmax over warp (lanes >= 27 -> exp underflow to 0)
        float mx = logit;
#pragma unroll
        for (int o = 16; o; o >>= 1)
            mx = fmaxf(mx, __shfl_xor_sync(~0u, mx, o));
        float e = __expf(logit - mx);
        float ssum = e;
#pragma unroll
        for (int o = 16; o; o >>= 1)
            ssum += __shfl_xor_sync(~0u, ssum, o);
        float aff = e / ssum;

        // aggregate Vo (two accumulators for chain ILP)
        float2 r = *(const float2*)&g_Vo[((unsigned)p << 6) + lrow];
        float2 r2 = make_float2(0.f, 0.f);
#pragma unroll
        for (int k = 0; k < KN; k += 2) {
            float aa = __shfl_sync(~0u, aff, k);
            int   pk = __shfl_sync(~0u, packed, k);
            float2 v = *(const float2*)&g_Vo[(((unsigned)pk & 0x1FFFFu) << 6) + lrow];
            r.x = fmaf(aa, v.x, r.x); r.y = fmaf(aa, v.y, r.y);
            if (k + 1 < KN) {
                float ab = __shfl_sync(~0u, aff, k + 1);
                int   pb = __shfl_sync(~0u, packed, k + 1);
                float2 w = *(const float2*)&g_Vo[(((unsigned)pb & 0x1FFFFu) << 6) + lrow];
                r2.x = fmaf(ab, w.x, r2.x); r2.y = fmaf(ab, w.y, r2.y);
            }
        }
        r.x += r2.x; r.y += r2.y;

        *(float2*)&out[off_ref + ((size_t)p << 6) + lrow] =
            make_float2(r.x + bo2.x, r.y + bo2.y);
        if (lane < KN) {
            size_t a = (size_t)p * KN + lane;
            out[off_aff + a] = aff;
            out[off_nbr + a] = (float)(packed & 0x1FFFF);
            out[off_msk + a] = (packed >> 22) ? 1.f : 0.f;
        }
    }
}

// ---------------------------------------------------------------------------
// Kernel C: logits = refined_feat @ Wc + bc  (reads refined from out buffer)
// ---------------------------------------------------------------------------
__global__ void __launch_bounds__(256) kC(
    const float* __restrict__ Wc, const float* __restrict__ bc,
    float* __restrict__ out)
{
    __shared__ float sWc[832];
    __shared__ float sBc[16];
    __shared__ float stage[8 * 256];
    for (int i = threadIdx.x; i < 832; i += 256) sWc[i] = Wc[i];
    if (threadIdx.x < 16) sBc[threadIdx.x] = (threadIdx.x < 13) ? bc[threadIdx.x] : 0.f;
    __syncthreads();

    const int lane = threadIdx.x & 31;
    float* myS = stage + (threadIdx.x >> 5) * 256;
    const int warp = (blockIdx.x * blockDim.x + threadIdx.x) >> 5;
    const int nw   = (gridDim.x * blockDim.x) >> 5;
    const float* refv = out + (size_t)41 * MPTS;

    for (int p4 = warp * 4; p4 < MPTS; p4 += nw * 4) {
        {
            const float4* rs = (const float4*)(refv + (size_t)p4 * 64);
            float4* sdst = (float4*)myS;
            sdst[lane]      = rs[lane];
            sdst[lane + 32] = rs[lane + 32];
        }
        __syncwarp();

        float c[4];
#pragma unroll
        for (int j = 0; j < 4; j++) c[j] = (lane < 13) ? sBc[lane] : 0.f;
#pragma unroll
        for (int i = 0; i < 64; i += 4) {
            float xj[4][4];
#pragma unroll
            for (int j = 0; j < 4; j++) {
                float4 t = *(const float4*)&myS[j * 64 + i];
                xj[j][0] = t.x; xj[j][1] = t.y; xj[j][2] = t.z; xj[j][3] = t.w;
            }
#pragma unroll
            for (int s = 0; s < 4; s++) {
                float w = (lane < 13) ? sWc[(i + s) * 13 + lane] : 0.f;
#pragma unroll
                for (int j = 0; j < 4; j++) c[j] = fmaf(xj[j][s], w, c[j]);
            }
        }
        __syncwarp();
        if (lane < 13) {
#pragma unroll
            for (int j = 0; j < 4; j++)
                out[(size_t)(p4 + j) * 13 + lane] = c[j];
        }
    }
}

extern "C" void kernel_launch(void* const* d_in, const int* in_sizes, int n_in,
                              void* d_out, int out_size)
{
    const float* geo    = (const float*)d_in[0];
    const float* sem    = (const float*)d_in[1];
    const int*   coords = (const int*)d_in[2];
    const int*   nbr    = (const int*)d_in[3];   // int32 (JAX x64 off)
    const float* Wg     = (const float*)d_in[4];
    const float* gam    = (const float*)d_in[5];
    const float* bet    = (const float*)d_in[6];
    const float* Wb     = (const float*)d_in[7];
    const float* bb     = (const float*)d_in[8];
    const float* Wq     = (const float*)d_in[9];
    const float* Wk     = (const float*)d_in[10];
    const float* Wv     = (const float*)d_in[11];
    const float* pe     = (const float*)d_in[12];
    const float* Wo     = (const float*)d_in[13];
    const float* bo     = (const float*)d_in[14];
    const float* Wc     = (const float*)d_in[15];
    const float* bc     = (const float*)d_in[16];
    float* out = (float*)d_out;

    const int smemA1 = 16576 * 4;   // 66304 B
    const int smemA2 = 9216 * 4;    // 36864 B
    cudaFuncSetAttribute(kA1, cudaFuncAttributeMaxDynamicSharedMemorySize, smemA1);

    kW<<<64, 256>>>(Wv, Wo, Wq, pe, coords);
    kA1<<<592, 256, smemA1>>>(geo, Wg, gam, bet, Wb, bb, Wq, Wk, out);
    kA2<<<592, 256, smemA2>>>(sem);
    kB<<<12500, 256>>>(nbr, bo, out);
    kC<<<592, 256>>>(Wc, bc, out);
}

// round 13
// speedup vs baseline: 1.1992x; 1.0749x over previous
#include <cuda_runtime.h>
#include <cuda_fp16.h>

#define MPTS 100000
#define KN   27

// Scratch (__device__ globals)
__device__ float   g_Qp[MPTS * 64];
__device__ __half2 g_Kbh[MPTS * 32];
__device__ __half2 g_Voh[MPTS * 32];
__device__ float   g_QPE[MPTS * 32];
__device__ int     g_cpack[MPTS];
__device__ float   g_Wvo[96 * 64];
__device__ float   g_Wqpe[64 * 32];

// ---------------------------------------------------------------------------
// Kernel W: fold W_vo = Wv@Wo [96,64], Wqpe[i][pos] = Wq[i,:]·pe[pos,:],
//           and pack coords into one int per point.
// ---------------------------------------------------------------------------
__global__ void kW(const float* __restrict__ Wv, const float* __restrict__ Wo,
                   const float* __restrict__ Wq, const float* __restrict__ pe,
                   const int* __restrict__ coords)
{
    int t = blockIdx.x * 256 + threadIdx.x;
    if (t < 96 * 64) {
        int row = t >> 6, col = t & 63;
        float s = 0.f;
#pragma unroll 16
        for (int i = 0; i < 64; i++)
            s = fmaf(Wv[row * 64 + i], Wo[i * 64 + col], s);
        g_Wvo[t] = s;
    } else if (t < 96 * 64 + 64 * 32) {
        int u = t - 96 * 64;
        int i = u >> 5, pos = u & 31;
        float s = 0.f;
        if (pos < KN) {
#pragma unroll 16
            for (int j = 0; j < 64; j++)
                s = fmaf(Wq[i * 64 + j], pe[pos * 64 + j], s);
        }
        g_Wqpe[u] = s;
    }
    for (int p = t; p < MPTS; p += gridDim.x * 256) {
        int x = coords[3 * p], y = coords[3 * p + 1], z = coords[3 * p + 2];
        g_cpack[p] = x | (y << 8) | (z << 16);
    }
}

// ---------------------------------------------------------------------------
// Kernel A1: 4 points/warp.  a = geo@Wg -> LN -> relu -> q
//   bdy = q@Wb+bb ; Qp = q@Wq ; Kb(h) = q@Wk ; QPE = q@Wqpe
// ---------------------------------------------------------------------------
__global__ void __launch_bounds__(256) kA1(
    const float* __restrict__ geo, const float* __restrict__ Wg,
    const float* __restrict__ gam, const float* __restrict__ bet,
    const float* __restrict__ Wb, const float* __restrict__ bb,
    const float* __restrict__ Wq, const float* __restrict__ Wk,
    float* __restrict__ out)
{
    extern __shared__ float sm[];
    float* sWg = sm;            // 4096
    float* sWq = sm + 4096;     // 4096
    float* sWk = sm + 8192;     // 4096
    float* sWqpe = sm + 12288;  // 2048
    float* sGm = sm + 14336;    // 64
    float* sBt = sm + 14400;    // 64
    float* sWb = sm + 14464;    // 64
    float* stage = sm + 14528;  // 8 warps * 256

    for (int i = threadIdx.x; i < 4096; i += 256) {
        sWg[i] = Wg[i]; sWq[i] = Wq[i]; sWk[i] = Wk[i];
    }
    for (int i = threadIdx.x; i < 2048; i += 256) sWqpe[i] = g_Wqpe[i];
    if (threadIdx.x < 64) {
        sGm[threadIdx.x] = gam[threadIdx.x];
        sBt[threadIdx.x] = bet[threadIdx.x];
        sWb[threadIdx.x] = Wb[threadIdx.x];
    }
    __syncthreads();

    const int lane = threadIdx.x & 31;
    float* myS = stage + (threadIdx.x >> 5) * 256;
    const int warp = (blockIdx.x * blockDim.x + threadIdx.x) >> 5;
    const int nw   = (gridDim.x * blockDim.x) >> 5;
    const float bb0 = bb[0];
    const float2 gm = *(const float2*)&sGm[2 * lane];
    const float2 bt = *(const float2*)&sBt[2 * lane];
    const float2 wb = *(const float2*)&sWb[2 * lane];

    for (int p4 = warp * 4; p4 < MPTS; p4 += nw * 4) {
        {
            const float4* gsrc = (const float4*)(geo + (size_t)p4 * 64);
            float4* sdst = (float4*)myS;
            sdst[lane]      = gsrc[lane];
            sdst[lane + 32] = gsrc[lane + 32];
        }
        __syncwarp();

        float a0[4] = {0,0,0,0}, a1[4] = {0,0,0,0};
#pragma unroll
        for (int i = 0; i < 64; i += 4) {
            float xj[4][4];
#pragma unroll
            for (int j = 0; j < 4; j++) {
                float4 t = *(const float4*)&myS[j * 64 + i];
                xj[j][0] = t.x; xj[j][1] = t.y; xj[j][2] = t.z; xj[j][3] = t.w;
            }
#pragma unroll
            for (int s = 0; s < 4; s++) {
                float2 w = *(const float2*)&sWg[(i + s) * 64 + 2 * lane];
#pragma unroll
                for (int j = 0; j < 4; j++) {
                    a0[j] = fmaf(xj[j][s], w.x, a0[j]);
                    a1[j] = fmaf(xj[j][s], w.y, a1[j]);
                }
            }
        }
        __syncwarp();

        float t[4];
#pragma unroll
        for (int j = 0; j < 4; j++) t[j] = a0[j] + a1[j];
#pragma unroll
        for (int o = 16; o; o >>= 1)
#pragma unroll
            for (int j = 0; j < 4; j++) t[j] += __shfl_xor_sync(~0u, t[j], o);
        float q0[4], q1[4], vr[4];
#pragma unroll
        for (int j = 0; j < 4; j++) {
            float mu = t[j] * (1.f / 64.f);
            a0[j] -= mu; a1[j] -= mu;
            vr[j] = a0[j] * a0[j] + a1[j] * a1[j];
        }
#pragma unroll
        for (int o = 16; o; o >>= 1)
#pragma unroll
            for (int j = 0; j < 4; j++) vr[j] += __shfl_xor_sync(~0u, vr[j], o);
#pragma unroll
        for (int j = 0; j < 4; j++) {
            float rs = rsqrtf(vr[j] * (1.f / 64.f) + 1e-5f);
            q0[j] = fmaxf(fmaf(a0[j] * rs, gm.x, bt.x), 0.f);
            q1[j] = fmaxf(fmaf(a1[j] * rs, gm.y, bt.y), 0.f);
        }

        float bd[4];
#pragma unroll
        for (int j = 0; j < 4; j++) bd[j] = q0[j] * wb.x + q1[j] * wb.y;
#pragma unroll
        for (int o = 16; o; o >>= 1)
#pragma unroll
            for (int j = 0; j < 4; j++) bd[j] += __shfl_xor_sync(~0u, bd[j], o);
        if (lane == 0) {
#pragma unroll
            for (int j = 0; j < 4; j++)
                out[(size_t)13 * MPTS + p4 + j] = bd[j] + bb0;
        }

#pragma unroll
        for (int j = 0; j < 4; j++)
            *(float2*)&myS[j * 64 + 2 * lane] = make_float2(q0[j], q1[j]);
        __syncwarp();

        float u0[4] = {0,0,0,0}, u1[4] = {0,0,0,0};
        float v0[4] = {0,0,0,0}, v1[4] = {0,0,0,0};
        float c[4]  = {0,0,0,0};
#pragma unroll
        for (int i = 0; i < 64; i += 4) {
            float xj[4][4];
#pragma unroll
            for (int j = 0; j < 4; j++) {
                float4 tt = *(const float4*)&myS[j * 64 + i];
                xj[j][0] = tt.x; xj[j][1] = tt.y; xj[j][2] = tt.z; xj[j][3] = tt.w;
            }
#pragma unroll
            for (int s = 0; s < 4; s++) {
                float2 wq = *(const float2*)&sWq[(i + s) * 64 + 2 * lane];
                float2 wk = *(const float2*)&sWk[(i + s) * 64 + 2 * lane];
                float wpe = sWqpe[(i + s) * 32 + lane];
#pragma unroll
                for (int j = 0; j < 4; j++) {
                    u0[j] = fmaf(xj[j][s], wq.x, u0[j]);
                    u1[j] = fmaf(xj[j][s], wq.y, u1[j]);
                    v0[j] = fmaf(xj[j][s], wk.x, v0[j]);
                    v1[j] = fmaf(xj[j][s], wk.y, v1[j]);
                    c[j]  = fmaf(xj[j][s], wpe, c[j]);
                }
            }
        }
        __syncwarp();
#pragma unroll
        for (int j = 0; j < 4; j++) {
            unsigned p = p4 + j;
            *(float2*)&g_Qp[((size_t)p << 6) + 2 * lane] = make_float2(u0[j], u1[j]);
            g_Kbh[(p << 5) + lane] = __floats2half2_rn(v0[j], v1[j]);
            g_QPE[((size_t)p << 5) + lane] = c[j];
        }
    }
}

// ---------------------------------------------------------------------------
// Kernel A2: 4 points/warp.  Vo = sem @ W_vo  (stored fp16 half2)
// ---------------------------------------------------------------------------
__global__ void __launch_bounds__(256) kA2(const float* __restrict__ sem)
{
    extern __shared__ float sm[];
    float* sW = sm;             // 6144
    float* stage = sm + 6144;   // 8 warps * 384

    for (int i = threadIdx.x; i < 6144; i += 256) sW[i] = g_Wvo[i];
    __syncthreads();

    const int lane = threadIdx.x & 31;
    float* myS = stage + (threadIdx.x >> 5) * 384;
    const int warp = (blockIdx.x * blockDim.x + threadIdx.x) >> 5;
    const int nw   = (gridDim.x * blockDim.x) >> 5;

    for (int p4 = warp * 4; p4 < MPTS; p4 += nw * 4) {
        {
            const float4* ssrc = (const float4*)(sem + (size_t)p4 * 96);
            float4* sdst = (float4*)myS;
            sdst[lane]      = ssrc[lane];
            sdst[lane + 32] = ssrc[lane + 32];
            sdst[lane + 64] = ssrc[lane + 64];
        }
        __syncwarp();

        float o0[4] = {0,0,0,0}, o1[4] = {0,0,0,0};
#pragma unroll
        for (int i = 0; i < 96; i += 4) {
            float xj[4][4];
#pragma unroll
            for (int j = 0; j < 4; j++) {
                float4 t = *(const float4*)&myS[j * 96 + i];
                xj[j][0] = t.x; xj[j][1] = t.y; xj[j][2] = t.z; xj[j][3] = t.w;
            }
#pragma unroll
            for (int s = 0; s < 4; s++) {
                float2 w = *(const float2*)&sW[(i + s) * 64 + 2 * lane];
#pragma unroll
                for (int j = 0; j < 4; j++) {
                    o0[j] = fmaf(xj[j][s], w.x, o0[j]);
                    o1[j] = fmaf(xj[j][s], w.y, o1[j]);
                }
            }
        }
        __syncwarp();
#pragma unroll
        for (int j = 0; j < 4; j++)
            g_Voh[((unsigned)(p4 + j) << 5) + lane] = __floats2half2_rn(o0[j], o1[j]);
    }
}

// ---------------------------------------------------------------------------
// Kernel B: attention, 1 point/warp.
// fp16 Kb/Vo gathers (128B rows, 1 wavefront each); XOR-swizzled sPart
// (phase-1 STS conflict-free, phase-2 LDS.128 at structural floor).
// ---------------------------------------------------------------------------
__global__ void __launch_bounds__(256, 5) kB(
    const int* __restrict__ nbr, const float* __restrict__ bo,
    float* __restrict__ out)
{
    __shared__ float sBo[64];
    __shared__ float sPart[8][28 * 32];   // packed rows of 32, XOR-swizzled chunks

    if (threadIdx.x < 64) sBo[threadIdx.x] = bo[threadIdx.x];
    __syncthreads();

    const int lane = threadIdx.x & 31;
    float* part = sPart[threadIdx.x >> 5];
    const int warp = (blockIdx.x * blockDim.x + threadIdx.x) >> 5;
    const int nw   = (gridDim.x * blockDim.x) >> 5;
    const float2 bo2 = *(const float2*)&sBo[2 * lane];
    const int chunk = lane >> 2, within = lane & 3;

    const size_t off_aff = (size_t)14 * MPTS;
    const size_t off_ref = (size_t)41 * MPTS;
    const size_t off_nbr = (size_t)105 * MPTS;
    const size_t off_msk = (size_t)132 * MPTS;

    for (int p = warp; p < MPTS; p += nw) {
        float2 q = *(const float2*)&g_Qp[((size_t)p << 6) + 2 * lane];
        float qpe_l = g_QPE[((size_t)p << 5) + lane];

        int cp = g_cpack[p];
        int cx = cp & 255, cy = (cp >> 8) & 255, cz = (cp >> 16) & 255;

        // pack = idx | pos<<17 | valid<<22  (idx < 2^17)
        int packed = 0;
        if (lane < KN) {
            int idx = nbr[(size_t)p * KN + lane];
            int np = g_cpack[idx];
            int rx = (np & 255) - cx;
            int ry = ((np >> 8) & 255) - cy;
            int rz = ((np >> 16) & 255) - cz;
            int vld = (max(abs(rx), max(abs(ry), abs(rz))) <= 1);
            int pos = min(max(rx + 1, 0), 2) * 9 + min(max(ry + 1, 0), 2) * 3
                    + min(max(rz + 1, 0), 2);
            packed = idx | (pos << 17) | (vld << 22);
        }

        // phase 1: fp16 gather dot, XOR-swizzled STS (conflict-free)
#pragma unroll
        for (int k = 0; k < KN; k++) {
            int pk = __shfl_sync(~0u, packed, k);
            unsigned idx = (unsigned)(pk & 0x1FFFF);
            float2 kf = __half22float2(g_Kbh[(idx << 5) + lane]);
            part[(k << 5) + (((chunk ^ (k & 7)) << 2) | within)] =
                q.x * kf.x + q.y * kf.y;
        }
        __syncwarp();

        // pe term for my neighbor
        int mypos = (packed >> 17) & 31;
        float qpe_mine = __shfl_sync(~0u, qpe_l, mypos);

        // phase 2: lane k sums its row (chunks in swizzled order)
        float logit = -1e30f;
        if (lane < KN) {
            const float* rw = part + (lane << 5);
            int sw = lane & 7;
            float4 t0 = *(const float4*)(rw + ((0 ^ sw) << 2));
            float4 t1 = *(const float4*)(rw + ((1 ^ sw) << 2));
            float4 t2 = *(const float4*)(rw + ((2 ^ sw) << 2));
            float4 t3 = *(const float4*)(rw + ((3 ^ sw) << 2));
            float4 t4 = *(const float4*)(rw + ((4 ^ sw) << 2));
            float4 t5 = *(const float4*)(rw + ((5 ^ sw) << 2));
            float4 t6 = *(const float4*)(rw + ((6 ^ sw) << 2));
            float4 t7 = *(const float4*)(rw + ((7 ^ sw) << 2));
            float s01 = (t0.x + t0.y) + (t0.z + t0.w) + (t1.x + t1.y) + (t1.z + t1.w);
            float s23 = (t2.x + t2.y) + (t2.z + t2.w) + (t3.x + t3.y) + (t3.z + t3.w);
            float s45 = (t4.x + t4.y) + (t4.z + t4.w) + (t5.x + t5.y) + (t5.z + t5.w);
            float s67 = (t6.x + t6.y) + (t6.z + t6.w) + (t7.x + t7.y) + (t7.z + t7.w);
            float s = (s01 + s23) + (s45 + s67) + qpe_mine;
            logit = (packed >> 22) ? s * 0.125f : -10000.0f;
        }
        __syncwarp();

        // softmax over warp (lanes >= 27 -> exp underflow to 0)
        float mx = logit;
#pragma unroll
        for (int o = 16; o; o >>= 1)
            mx = fmaxf(mx, __shfl_xor_sync(~0u, mx, o));
        float e = __expf(logit - mx);
        float ssum = e;
#pragma unroll
        for (int o = 16; o; o >>= 1)
            ssum += __shfl_xor_sync(~0u, ssum, o);
        float aff = e / ssum;

        // aggregate Vo (fp16 gathers, fp32 accumulate, 2 chains)
        float2 r = __half22float2(g_Voh[((unsigned)p << 5) + lane]);
        float2 r2 = make_float2(0.f, 0.f);
#pragma unroll
        for (int k = 0; k < KN; k += 2) {
            float aa = __shfl_sync(~0u, aff, k);
            int   pk = __shfl_sync(~0u, packed, k);
            float2 v = __half22float2(g_Voh[(((unsigned)pk & 0x1FFFFu) << 5) + lane]);
            r.x = fmaf(aa, v.x, r.x); r.y = fmaf(aa, v.y, r.y);
            if (k + 1 < KN) {
                float ab = __shfl_sync(~0u, aff, k + 1);
                int   pb = __shfl_sync(~0u, packed, k + 1);
                float2 w = __half22float2(g_Voh[(((unsigned)pb & 0x1FFFFu) << 5) + lane]);
                r2.x = fmaf(ab, w.x, r2.x); r2.y = fmaf(ab, w.y, r2.y);
            }
        }
        r.x += r2.x; r.y += r2.y;

        *(float2*)&out[off_ref + ((size_t)p << 6) + 2 * lane] =
            make_float2(r.x + bo2.x, r.y + bo2.y);
        if (lane < KN) {
            size_t a = (size_t)p * KN + lane;
            out[off_aff + a] = aff;
            out[off_nbr + a] = (float)(packed & 0x1FFFF);
            out[off_msk + a] = (packed >> 22) ? 1.f : 0.f;
        }
    }
}

// ---------------------------------------------------------------------------
// Kernel C: logits = refined_feat @ Wc + bc  (reads refined from out buffer)
// ---------------------------------------------------------------------------
__global__ void __launch_bounds__(256) kC(
    const float* __restrict__ Wc, const float* __restrict__ bc,
    float* __restrict__ out)
{
    __shared__ float sWc[832];
    __shared__ float sBc[16];
    __shared__ float stage[8 * 256];
    for (int i = threadIdx.x; i < 832; i += 256) sWc[i] = Wc[i];
    if (threadIdx.x < 16) sBc[threadIdx.x] = (threadIdx.x < 13) ? bc[threadIdx.x] : 0.f;
    __syncthreads();

    const int lane = threadIdx.x & 31;
    float* myS = stage + (threadIdx.x >> 5) * 256;
    const int warp = (blockIdx.x * blockDim.x + threadIdx.x) >> 5;
    const int nw   = (gridDim.x * blockDim.x) >> 5;
    const float* refv = out + (size_t)41 * MPTS;

    for (int p4 = warp * 4; p4 < MPTS; p4 += nw * 4) {
        {
            const float4* rs = (const float4*)(refv + (size_t)p4 * 64);
            float4* sdst = (float4*)myS;
            sdst[lane]      = rs[lane];
            sdst[lane + 32] = rs[lane + 32];
        }
        __syncwarp();

        float c[4];
#pragma unroll
        for (int j = 0; j < 4; j++) c[j] = (lane < 13) ? sBc[lane] : 0.f;
#pragma unroll
        for (int i = 0; i < 64; i += 4) {
            float xj[4][4];
#pragma unroll
            for (int j = 0; j < 4; j++) {
                float4 t = *(const float4*)&myS[j * 64 + i];
                xj[j][0] = t.x; xj[j][1] = t.y; xj[j][2] = t.z; xj[j][3] = t.w;
            }
#pragma unroll
            for (int s = 0; s < 4; s++) {
                float w = (lane < 13) ? sWc[(i + s) * 13 + lane] : 0.f;
#pragma unroll
                for (int j = 0; j < 4; j++) c[j] = fmaf(xj[j][s], w, c[j]);
            }
        }
        __syncwarp();
        if (lane < 13) {
#pragma unroll
            for (int j = 0; j < 4; j++)
                out[(size_t)(p4 + j) * 13 + lane] = c[j];
        }
    }
}

extern "C" void kernel_launch(void* const* d_in, const int* in_sizes, int n_in,
                              void* d_out, int out_size)
{
    const float* geo    = (const float*)d_in[0];
    const float* sem    = (const float*)d_in[1];
    const int*   coords = (const int*)d_in[2];
    const int*   nbr    = (const int*)d_in[3];   // int32 (JAX x64 off)
    const float* Wg     = (const float*)d_in[4];
    const float* gam    = (const float*)d_in[5];
    const float* bet    = (const float*)d_in[6];
    const float* Wb     = (const float*)d_in[7];
    const float* bb     = (const float*)d_in[8];
    const float* Wq     = (const float*)d_in[9];
    const float* Wk     = (const float*)d_in[10];
    const float* Wv     = (const float*)d_in[11];
    const float* pe     = (const float*)d_in[12];
    const float* Wo     = (const float*)d_in[13];
    const float* bo     = (const float*)d_in[14];
    const float* Wc     = (const float*)d_in[15];
    const float* bc     = (const float*)d_in[16];
    float* out = (float*)d_out;

    const int smemA1 = 16576 * 4;   // 66304 B
    const int smemA2 = 9216 * 4;    // 36864 B
    cudaFuncSetAttribute(kA1, cudaFuncAttributeMaxDynamicSharedMemorySize, smemA1);
    cudaFuncSetAttribute(kA2, cudaFuncAttributeMaxDynamicSharedMemorySize, smemA2);

    kW<<<64, 256>>>(Wv, Wo, Wq, pe, coords);
    kA1<<<592, 256, smemA1>>>(geo, Wg, gam, bet, Wb, bb, Wq, Wk, out);
    kA2<<<592, 256, smemA2>>>(sem);
    kB<<<12500, 256>>>(nbr, bo, out);
    kC<<<592, 256>>>(Wc, bc, out);
}

// round 14
// speedup vs baseline: 1.2183x; 1.0159x over previous
#include <cuda_runtime.h>
#include <cuda_fp16.h>

#define MPTS 100000
#define KN   27

// Scratch (__device__ globals)
__device__ float   g_Qp[MPTS * 64];
__device__ __half2 g_Kbh[MPTS * 32];
__device__ __half2 g_Voh[MPTS * 32];
__device__ float   g_QPE[MPTS * 32];
__device__ int     g_cpack[MPTS];
__device__ float   g_Wvo[96 * 64];
__device__ float   g_Wqpe[64 * 32];

// packed f32x2 helpers (sm_103a FFMA2 path)
__device__ __forceinline__ unsigned long long pk2(float lo, float hi) {
    unsigned long long r;
    asm("mov.b64 %0, {%1, %2};" : "=l"(r) : "f"(lo), "f"(hi));
    return r;
}
__device__ __forceinline__ void fma2(unsigned long long& d,
                                     unsigned long long a, unsigned long long b) {
    asm("fma.rn.f32x2 %0, %1, %2, %3;" : "=l"(d) : "l"(a), "l"(b), "l"(d));
}
__device__ __forceinline__ float2 upk2(unsigned long long v) {
    float2 f;
    asm("mov.b64 {%0, %1}, %2;" : "=f"(f.x), "=f"(f.y) : "l"(v));
    return f;
}

// ---------------------------------------------------------------------------
// Kernel W: fold W_vo = Wv@Wo [96,64], Wqpe[i][pos] = Wq[i,:]·pe[pos,:],
//           and pack coords into one int per point.
// ---------------------------------------------------------------------------
__global__ void kW(const float* __restrict__ Wv, const float* __restrict__ Wo,
                   const float* __restrict__ Wq, const float* __restrict__ pe,
                   const int* __restrict__ coords)
{
    int t = blockIdx.x * 256 + threadIdx.x;
    if (t < 96 * 64) {
        int row = t >> 6, col = t & 63;
        float s = 0.f;
#pragma unroll 16
        for (int i = 0; i < 64; i++)
            s = fmaf(Wv[row * 64 + i], Wo[i * 64 + col], s);
        g_Wvo[t] = s;
    } else if (t < 96 * 64 + 64 * 32) {
        int u = t - 96 * 64;
        int i = u >> 5, pos = u & 31;
        float s = 0.f;
        if (pos < KN) {
#pragma unroll 16
            for (int j = 0; j < 64; j++)
                s = fmaf(Wq[i * 64 + j], pe[pos * 64 + j], s);
        }
        g_Wqpe[u] = s;
    }
    for (int p = t; p < MPTS; p += gridDim.x * 256) {
        int x = coords[3 * p], y = coords[3 * p + 1], z = coords[3 * p + 2];
        g_cpack[p] = x | (y << 8) | (z << 16);
    }
}

// ---------------------------------------------------------------------------
// Kernel A1: 4 points/warp, packed-f32x2 accumulators (FFMA2).
//   a = geo@Wg -> LN -> relu -> q ; bdy ; Qp = q@Wq ; Kb(h) = q@Wk ; QPE
// ---------------------------------------------------------------------------
__global__ void __launch_bounds__(256) kA1(
    const float* __restrict__ geo, const float* __restrict__ Wg,
    const float* __restrict__ gam, const float* __restrict__ bet,
    const float* __restrict__ Wb, const float* __restrict__ bb,
    const float* __restrict__ Wq, const float* __restrict__ Wk,
    float* __restrict__ out)
{
    extern __shared__ float sm[];
    float* sWg = sm;            // 4096
    float* sWq = sm + 4096;     // 4096
    float* sWk = sm + 8192;     // 4096
    float* sWqpe = sm + 12288;  // 2048
    float* sGm = sm + 14336;    // 64
    float* sBt = sm + 14400;    // 64
    float* sWb = sm + 14464;    // 64
    float* stage = sm + 14528;  // 8 warps * 256

    for (int i = threadIdx.x; i < 4096; i += 256) {
        sWg[i] = Wg[i]; sWq[i] = Wq[i]; sWk[i] = Wk[i];
    }
    for (int i = threadIdx.x; i < 2048; i += 256) sWqpe[i] = g_Wqpe[i];
    if (threadIdx.x < 64) {
        sGm[threadIdx.x] = gam[threadIdx.x];
        sBt[threadIdx.x] = bet[threadIdx.x];
        sWb[threadIdx.x] = Wb[threadIdx.x];
    }
    __syncthreads();

    const int lane = threadIdx.x & 31;
    float* myS = stage + (threadIdx.x >> 5) * 256;
    const int warp = (blockIdx.x * blockDim.x + threadIdx.x) >> 5;
    const int nw   = (gridDim.x * blockDim.x) >> 5;
    const float bb0 = bb[0];
    const float2 gm = *(const float2*)&sGm[2 * lane];
    const float2 bt = *(const float2*)&sBt[2 * lane];
    const float2 wb = *(const float2*)&sWb[2 * lane];

    for (int p4 = warp * 4; p4 < MPTS; p4 += nw * 4) {
        {
            const float4* gsrc = (const float4*)(geo + (size_t)p4 * 64);
            float4* sdst = (float4*)myS;
            sdst[lane]      = gsrc[lane];
            sdst[lane + 32] = gsrc[lane + 32];
        }
        __syncwarp();

        unsigned long long a01[4] = {0, 0, 0, 0};
#pragma unroll
        for (int i = 0; i < 64; i += 4) {
            float xj[4][4];
#pragma unroll
            for (int j = 0; j < 4; j++) {
                float4 t = *(const float4*)&myS[j * 64 + i];
                xj[j][0] = t.x; xj[j][1] = t.y; xj[j][2] = t.z; xj[j][3] = t.w;
            }
#pragma unroll
            for (int s = 0; s < 4; s++) {
                unsigned long long w =
                    *(const unsigned long long*)&sWg[(i + s) * 64 + 2 * lane];
#pragma unroll
                for (int j = 0; j < 4; j++) {
                    unsigned long long xx = pk2(xj[j][s], xj[j][s]);
                    fma2(a01[j], xx, w);
                }
            }
        }
        __syncwarp();

        float a0[4], a1[4];
#pragma unroll
        for (int j = 0; j < 4; j++) {
            float2 av = upk2(a01[j]);
            a0[j] = av.x; a1[j] = av.y;
        }

        float t[4];
#pragma unroll
        for (int j = 0; j < 4; j++) t[j] = a0[j] + a1[j];
#pragma unroll
        for (int o = 16; o; o >>= 1)
#pragma unroll
            for (int j = 0; j < 4; j++) t[j] += __shfl_xor_sync(~0u, t[j], o);
        float q0[4], q1[4], vr[4];
#pragma unroll
        for (int j = 0; j < 4; j++) {
            float mu = t[j] * (1.f / 64.f);
            a0[j] -= mu; a1[j] -= mu;
            vr[j] = a0[j] * a0[j] + a1[j] * a1[j];
        }
#pragma unroll
        for (int o = 16; o; o >>= 1)
#pragma unroll
            for (int j = 0; j < 4; j++) vr[j] += __shfl_xor_sync(~0u, vr[j], o);
#pragma unroll
        for (int j = 0; j < 4; j++) {
            float rs = rsqrtf(vr[j] * (1.f / 64.f) + 1e-5f);
            q0[j] = fmaxf(fmaf(a0[j] * rs, gm.x, bt.x), 0.f);
            q1[j] = fmaxf(fmaf(a1[j] * rs, gm.y, bt.y), 0.f);
        }

        float bd[4];
#pragma unroll
        for (int j = 0; j < 4; j++) bd[j] = q0[j] * wb.x + q1[j] * wb.y;
#pragma unroll
        for (int o = 16; o; o >>= 1)
#pragma unroll
            for (int j = 0; j < 4; j++) bd[j] += __shfl_xor_sync(~0u, bd[j], o);
        if (lane == 0) {
#pragma unroll
            for (int j = 0; j < 4; j++)
                out[(size_t)13 * MPTS + p4 + j] = bd[j] + bb0;
        }

#pragma unroll
        for (int j = 0; j < 4; j++)
            *(float2*)&myS[j * 64 + 2 * lane] = make_float2(q0[j], q1[j]);
        __syncwarp();

        unsigned long long u01[4] = {0, 0, 0, 0};
        unsigned long long v01[4] = {0, 0, 0, 0};
        float c[4]  = {0, 0, 0, 0};
#pragma unroll
        for (int i = 0; i < 64; i += 4) {
            float xj[4][4];
#pragma unroll
            for (int j = 0; j < 4; j++) {
                float4 tt = *(const float4*)&myS[j * 64 + i];
                xj[j][0] = tt.x; xj[j][1] = tt.y; xj[j][2] = tt.z; xj[j][3] = tt.w;
            }
#pragma unroll
            for (int s = 0; s < 4; s++) {
                unsigned long long wq =
                    *(const unsigned long long*)&sWq[(i + s) * 64 + 2 * lane];
                unsigned long long wk =
                    *(const unsigned long long*)&sWk[(i + s) * 64 + 2 * lane];
                float wpe = sWqpe[(i + s) * 32 + lane];
#pragma unroll
                for (int j = 0; j < 4; j++) {
                    unsigned long long xx = pk2(xj[j][s], xj[j][s]);
                    fma2(u01[j], xx, wq);
                    fma2(v01[j], xx, wk);
                    c[j]  = fmaf(xj[j][s], wpe, c[j]);
                }
            }
        }
        __syncwarp();
#pragma unroll
        for (int j = 0; j < 4; j++) {
            unsigned p = p4 + j;
            *(unsigned long long*)&g_Qp[((size_t)p << 6) + 2 * lane] = u01[j];
            float2 vv = upk2(v01[j]);
            g_Kbh[(p << 5) + lane] = __floats2half2_rn(vv.x, vv.y);
            g_QPE[((size_t)p << 5) + lane] = c[j];
        }
    }
}

// ---------------------------------------------------------------------------
// Kernel A2: 4 points/warp.  Vo = sem @ W_vo  (packed FFMA2, stored fp16)
// ---------------------------------------------------------------------------
__global__ void __launch_bounds__(256) kA2(const float* __restrict__ sem)
{
    extern __shared__ float sm[];
    float* sW = sm;             // 6144
    float* stage = sm + 6144;   // 8 warps * 384

    for (int i = threadIdx.x; i < 6144; i += 256) sW[i] = g_Wvo[i];
    __syncthreads();

    const int lane = threadIdx.x & 31;
    float* myS = stage + (threadIdx.x >> 5) * 384;
    const int warp = (blockIdx.x * blockDim.x + threadIdx.x) >> 5;
    const int nw   = (gridDim.x * blockDim.x) >> 5;

    for (int p4 = warp * 4; p4 < MPTS; p4 += nw * 4) {
        {
            const float4* ssrc = (const float4*)(sem + (size_t)p4 * 96);
            float4* sdst = (float4*)myS;
            sdst[lane]      = ssrc[lane];
            sdst[lane + 32] = ssrc[lane + 32];
            sdst[lane + 64] = ssrc[lane + 64];
        }
        __syncwarp();

        unsigned long long o01[4] = {0, 0, 0, 0};
#pragma unroll
        for (int i = 0; i < 96; i += 4) {
            float xj[4][4];
#pragma unroll
            for (int j = 0; j < 4; j++) {
                float4 t = *(const float4*)&myS[j * 96 + i];
                xj[j][0] = t.x; xj[j][1] = t.y; xj[j][2] = t.z; xj[j][3] = t.w;
            }
#pragma unroll
            for (int s = 0; s < 4; s++) {
                unsigned long long w =
                    *(const unsigned long long*)&sW[(i + s) * 64 + 2 * lane];
#pragma unroll
                for (int j = 0; j < 4; j++) {
                    unsigned long long xx = pk2(xj[j][s], xj[j][s]);
                    fma2(o01[j], xx, w);
                }
            }
        }
        __syncwarp();
#pragma unroll
        for (int j = 0; j < 4; j++) {
            float2 ov = upk2(o01[j]);
            g_Voh[((unsigned)(p4 + j) << 5) + lane] = __floats2half2_rn(ov.x, ov.y);
        }
    }
}

// ---------------------------------------------------------------------------
// Kernel B: attention, 1 point/warp (unchanged from R13 winner).
// ---------------------------------------------------------------------------
__global__ void __launch_bounds__(256, 5) kB(
    const int* __restrict__ nbr, const float* __restrict__ bo,
    float* __restrict__ out)
{
    __shared__ float sBo[64];
    __shared__ float sPart[8][28 * 32];   // packed rows of 32, XOR-swizzled chunks

    if (threadIdx.x < 64) sBo[threadIdx.x] = bo[threadIdx.x];
    __syncthreads();

    const int lane = threadIdx.x & 31;
    float* part = sPart[threadIdx.x >> 5];
    const int warp = (blockIdx.x * blockDim.x + threadIdx.x) >> 5;
    const int nw   = (gridDim.x * blockDim.x) >> 5;
    const float2 bo2 = *(const float2*)&sBo[2 * lane];
    const int chunk = lane >> 2, within = lane & 3;

    const size_t off_aff = (size_t)14 * MPTS;
    const size_t off_ref = (size_t)41 * MPTS;
    const size_t off_nbr = (size_t)105 * MPTS;
    const size_t off_msk = (size_t)132 * MPTS;

    for (int p = warp; p < MPTS; p += nw) {
        float2 q = *(const float2*)&g_Qp[((size_t)p << 6) + 2 * lane];
        float qpe_l = g_QPE[((size_t)p << 5) + lane];

        int cp = g_cpack[p];
        int cx = cp & 255, cy = (cp >> 8) & 255, cz = (cp >> 16) & 255;

        int packed = 0;
        if (lane < KN) {
            int idx = nbr[(size_t)p * KN + lane];
            int np = g_cpack[idx];
            int rx = (np & 255) - cx;
            int ry = ((np >> 8) & 255) - cy;
            int rz = ((np >> 16) & 255) - cz;
            int vld = (max(abs(rx), max(abs(ry), abs(rz))) <= 1);
            int pos = min(max(rx + 1, 0), 2) * 9 + min(max(ry + 1, 0), 2) * 3
                    + min(max(rz + 1, 0), 2);
            packed = idx | (pos << 17) | (vld << 22);
        }

#pragma unroll
        for (int k = 0; k < KN; k++) {
            int pk = __shfl_sync(~0u, packed, k);
            unsigned idx = (unsigned)(pk & 0x1FFFF);
            float2 kf = __half22float2(g_Kbh[(idx << 5) + lane]);
            part[(k << 5) + (((chunk ^ (k & 7)) << 2) | within)] =
                q.x * kf.x + q.y * kf.y;
        }
        __syncwarp();

        int mypos = (packed >> 17) & 31;
        float qpe_mine = __shfl_sync(~0u, qpe_l, mypos);

        float logit = -1e30f;
        if (lane < KN) {
            const float* rw = part + (lane << 5);
            int sw = lane & 7;
            float4 t0 = *(const float4*)(rw + ((0 ^ sw) << 2));
            float4 t1 = *(const float4*)(rw + ((1 ^ sw) << 2));
            float4 t2 = *(const float4*)(rw + ((2 ^ sw) << 2));
            float4 t3 = *(const float4*)(rw + ((3 ^ sw) << 2));
            float4 t4 = *(const float4*)(rw + ((4 ^ sw) << 2));
            float4 t5 = *(const float4*)(rw + ((5 ^ sw) << 2));
            float4 t6 = *(const float4*)(rw + ((6 ^ sw) << 2));
            float4 t7 = *(const float4*)(rw + ((7 ^ sw) << 2));
            float s01 = (t0.x + t0.y) + (t0.z + t0.w) + (t1.x + t1.y) + (t1.z + t1.w);
            float s23 = (t2.x + t2.y) + (t2.z + t2.w) + (t3.x + t3.y) + (t3.z + t3.w);
            float s45 = (t4.x + t4.y) + (t4.z + t4.w) + (t5.x + t5.y) + (t5.z + t5.w);
            float s67 = (t6.x + t6.y) + (t6.z + t6.w) + (t7.x + t7.y) + (t7.z + t7.w);
            float s = (s01 + s23) + (s45 + s67) + qpe_mine;
            logit = (packed >> 22) ? s * 0.125f : -10000.0f;
        }
        __syncwarp();

        float mx = logit;
#pragma unroll
        for (int o = 16; o; o >>= 1)
            mx = fmaxf(mx, __shfl_xor_sync(~0u, mx, o));
        float e = __expf(logit - mx);
        float ssum = e;
#pragma unroll
        for (int o = 16; o; o >>= 1)
            ssum += __shfl_xor_sync(~0u, ssum, o);
        float aff = e / ssum;

        float2 r = __half22float2(g_Voh[((unsigned)p << 5) + lane]);
        float2 r2 = make_float2(0.f, 0.f);
#pragma unroll
        for (int k = 0; k < KN; k += 2) {
            float aa = __shfl_sync(~0u, aff, k);
            int   pk = __shfl_sync(~0u, packed, k);
            float2 v = __half22float2(g_Voh[(((unsigned)pk & 0x1FFFFu) << 5) + lane]);
            r.x = fmaf(aa, v.x, r.x); r.y = fmaf(aa, v.y, r.y);
            if (k + 1 < KN) {
                float ab = __shfl_sync(~0u, aff, k + 1);
                int   pb = __shfl_sync(~0u, packed, k + 1);
                float2 w = __half22float2(g_Voh[(((unsigned)pb & 0x1FFFFu) << 5) + lane]);
                r2.x = fmaf(ab, w.x, r2.x); r2.y = fmaf(ab, w.y, r2.y);
            }
        }
        r.x += r2.x; r.y += r2.y;

        *(float2*)&out[off_ref + ((size_t)p << 6) + 2 * lane] =
            make_float2(r.x + bo2.x, r.y + bo2.y);
        if (lane < KN) {
            size_t a = (size_t)p * KN + lane;
            out[off_aff + a] = aff;
            out[off_nbr + a] = (float)(packed & 0x1FFFF);
            out[off_msk + a] = (packed >> 22) ? 1.f : 0.f;
        }
    }
}

// ---------------------------------------------------------------------------
// Kernel C: logits = refined_feat @ Wc + bc  (reads refined from out buffer)
// ---------------------------------------------------------------------------
__global__ void __launch_bounds__(256) kC(
    const float* __restrict__ Wc, const float* __restrict__ bc,
    float* __restrict__ out)
{
    __shared__ float sWc[832];
    __shared__ float sBc[16];
    __shared__ float stage[8 * 256];
    for (int i = threadIdx.x; i < 832; i += 256) sWc[i] = Wc[i];
    if (threadIdx.x < 16) sBc[threadIdx.x] = (threadIdx.x < 13) ? bc[threadIdx.x] : 0.f;
    __syncthreads();

    const int lane = threadIdx.x & 31;
    float* myS = stage + (threadIdx.x >> 5) * 256;
    const int warp = (blockIdx.x * blockDim.x + threadIdx.x) >> 5;
    const int nw   = (gridDim.x * blockDim.x) >> 5;
    const float* refv = out + (size_t)41 * MPTS;

    for (int p4 = warp * 4; p4 < MPTS; p4 += nw * 4) {
        {
            const float4* rs = (const float4*)(refv + (size_t)p4 * 64);
            float4* sdst = (float4*)myS;
            sdst[lane]      = rs[lane];
            sdst[lane + 32] = rs[lane + 32];
        }
        __syncwarp();

        float c[4];
#pragma unroll
        for (int j = 0; j < 4; j++) c[j] = (lane < 13) ? sBc[lane] : 0.f;
#pragma unroll
        for (int i = 0; i < 64; i += 4) {
            float xj[4][4];
#pragma unroll
            for (int j = 0; j < 4; j++) {
                float4 t = *(const float4*)&myS[j * 64 + i];
                xj[j][0] = t.x; xj[j][1] = t.y; xj[j][2] = t.z; xj[j][3] = t.w;
            }
#pragma unroll
            for (int s = 0; s < 4; s++) {
                float w = (lane < 13) ? sWc[(i + s) * 13 + lane] : 0.f;
#pragma unroll
                for (int j = 0; j < 4; j++) c[j] = fmaf(xj[j][s], w, c[j]);
            }
        }
        __syncwarp();
        if (lane < 13) {
#pragma unroll
            for (int j = 0; j < 4; j++)
                out[(size_t)(p4 + j) * 13 + lane] = c[j];
        }
    }
}

extern "C" void kernel_launch(void* const* d_in, const int* in_sizes, int n_in,
                              void* d_out, int out_size)
{
    const float* geo    = (const float*)d_in[0];
    const float* sem    = (const float*)d_in[1];
    const int*   coords = (const int*)d_in[2];
    const int*   nbr    = (const int*)d_in[3];   // int32 (JAX x64 off)
    const float* Wg     = (const float*)d_in[4];
    const float* gam    = (const float*)d_in[5];
    const float* bet    = (const float*)d_in[6];
    const float* Wb     = (const float*)d_in[7];
    const float* bb     = (const float*)d_in[8];
    const float* Wq     = (const float*)d_in[9];
    const float* Wk     = (const float*)d_in[10];
    const float* Wv     = (const float*)d_in[11];
    const float* pe     = (const float*)d_in[12];
    const float* Wo     = (const float*)d_in[13];
    const float* bo     = (const float*)d_in[14];
    const float* Wc     = (const float*)d_in[15];
    const float* bc     = (const float*)d_in[16];
    float* out = (float*)d_out;

    const int smemA1 = 16576 * 4;   // 66304 B
    const int smemA2 = 9216 * 4;    // 36864 B
    cudaFuncSetAttribute(kA1, cudaFuncAttributeMaxDynamicSharedMemorySize, smemA1);
    cudaFuncSetAttribute(kA2, cudaFuncAttributeMaxDynamicSharedMemorySize, smemA2);

    kW<<<64, 256>>>(Wv, Wo, Wq, pe, coords);
    kA1<<<592, 256, smemA1>>>(geo, Wg, gam, bet, Wb, bb, Wq, Wk, out);
    kA2<<<592, 256, smemA2>>>(sem);
    kB<<<12500, 256>>>(nbr, bo, out);
    kC<<<592, 256>>>(Wc, bc, out);
}

// round 15
// speedup vs baseline: 1.2361x; 1.0147x over previous
#include <cuda_runtime.h>
#include <cuda_fp16.h>

#define MPTS 100000
#define KN   27

// Scratch (__device__ globals)
__device__ float   g_Qp[MPTS * 64];
__device__ __half2 g_Kbh[MPTS * 32];
__device__ __half2 g_Voh[MPTS * 32];
__device__ float   g_QPE[MPTS * 32];
__device__ int     g_cpack[MPTS];
__device__ float   g_Wvo[96 * 64];
__device__ float   g_Wqpe[64 * 32];

// packed f32x2 helpers (sm_103a FFMA2 path)
__device__ __forceinline__ void fma2(unsigned long long& d,
                                     unsigned long long a, unsigned long long b) {
    asm("fma.rn.f32x2 %0, %1, %2, %3;" : "=l"(d) : "l"(a), "l"(b), "l"(d));
}
__device__ __forceinline__ float hsum2(unsigned long long v) {
    float2 f;
    asm("mov.b64 {%0, %1}, %2;" : "=f"(f.x), "=f"(f.y) : "l"(v));
    return f.x + f.y;
}

// ---------------------------------------------------------------------------
// Kernel W: fold W_vo = Wv@Wo [96,64], Wqpe[i][pos] = Wq[i,:]·pe[pos,:],
//           and pack coords into one int per point.
// ---------------------------------------------------------------------------
__global__ void kW(const float* __restrict__ Wv, const float* __restrict__ Wo,
                   const float* __restrict__ Wq, const float* __restrict__ pe,
                   const int* __restrict__ coords)
{
    int t = blockIdx.x * 256 + threadIdx.x;
    if (t < 96 * 64) {
        int row = t >> 6, col = t & 63;
        float s = 0.f;
#pragma unroll 16
        for (int i = 0; i < 64; i++)
            s = fmaf(Wv[row * 64 + i], Wo[i * 64 + col], s);
        g_Wvo[t] = s;
    } else if (t < 96 * 64 + 64 * 32) {
        int u = t - 96 * 64;
        int i = u >> 5, pos = u & 31;
        float s = 0.f;
        if (pos < KN) {
#pragma unroll 16
            for (int j = 0; j < 64; j++)
                s = fmaf(Wq[i * 64 + j], pe[pos * 64 + j], s);
        }
        g_Wqpe[u] = s;
    }
    for (int p = t; p < MPTS; p += gridDim.x * 256) {
        int x = coords[3 * p], y = coords[3 * p + 1], z = coords[3 * p + 2];
        g_cpack[p] = x | (y << 8) | (z << 16);
    }
}

// ---------------------------------------------------------------------------
// Kernel A1: 4 points/warp, pair-major weights + FFMA2 (zero-pack GEMVs).
// Layout: W2[(i/2)*128 + c*2 + (i&1)] = W[i][c]; one LDS.128 per i-pair per
// lane yields the u64 operands for cols (2l, 2l+1). x-pairs come straight
// from staged ulonglong2 loads.
// ---------------------------------------------------------------------------
__global__ void __launch_bounds__(256) kA1(
    const float* __restrict__ geo, const float* __restrict__ Wg,
    const float* __restrict__ gam, const float* __restrict__ bet,
    const float* __restrict__ Wb, const float* __restrict__ bb,
    const float* __restrict__ Wq, const float* __restrict__ Wk,
    float* __restrict__ out)
{
    extern __shared__ float sm[];
    float* sWg = sm;            // 4096 (pair-major)
    float* sWq = sm + 4096;     // 4096 (pair-major)
    float* sWk = sm + 8192;     // 4096 (pair-major)
    float* sWqpe = sm + 12288;  // 2048 (pair-major, 32 cols)
    float* sGm = sm + 14336;    // 64
    float* sBt = sm + 14400;    // 64
    float* sWb = sm + 14464;    // 64
    float* stage = sm + 14528;  // 8 warps * 256

    for (int idx = threadIdx.x; idx < 4096; idx += 256) {
        int i = idx >> 6, c = idx & 63;
        int dst = (i >> 1) * 128 + c * 2 + (i & 1);
        sWg[dst] = Wg[idx];
        sWq[dst] = Wq[idx];
        sWk[dst] = Wk[idx];
    }
    for (int idx = threadIdx.x; idx < 2048; idx += 256) {
        int i = idx >> 5, c = idx & 31;
        sWqpe[(i >> 1) * 64 + c * 2 + (i & 1)] = g_Wqpe[idx];
    }
    if (threadIdx.x < 64) {
        sGm[threadIdx.x] = gam[threadIdx.x];
        sBt[threadIdx.x] = bet[threadIdx.x];
        sWb[threadIdx.x] = Wb[threadIdx.x];
    }
    __syncthreads();

    const int lane = threadIdx.x & 31;
    float* myS = stage + (threadIdx.x >> 5) * 256;
    const int warp = (blockIdx.x * blockDim.x + threadIdx.x) >> 5;
    const int nw   = (gridDim.x * blockDim.x) >> 5;
    const float bb0 = bb[0];
    const float2 gm = *(const float2*)&sGm[2 * lane];
    const float2 bt = *(const float2*)&sBt[2 * lane];
    const float2 wb = *(const float2*)&sWb[2 * lane];

    for (int p4 = warp * 4; p4 < MPTS; p4 += nw * 4) {
        {
            const float4* gsrc = (const float4*)(geo + (size_t)p4 * 64);
            float4* sdst = (float4*)myS;
            sdst[lane]      = gsrc[lane];
            sdst[lane + 32] = gsrc[lane + 32];
        }
        __syncwarp();

        // a = geo@Wg  (pair-major, zero packs)
        unsigned long long aL[4] = {0,0,0,0}, aH[4] = {0,0,0,0};
#pragma unroll
        for (int Q = 0; Q < 16; Q++) {
            ulonglong2 xv[4];
#pragma unroll
            for (int j = 0; j < 4; j++)
                xv[j] = *(const ulonglong2*)&myS[j * 64 + 4 * Q];
            ulonglong2 wA = *(const ulonglong2*)&sWg[(2 * Q) * 128 + 4 * lane];
            ulonglong2 wB = *(const ulonglong2*)&sWg[(2 * Q + 1) * 128 + 4 * lane];
#pragma unroll
            for (int j = 0; j < 4; j++) {
                fma2(aL[j], xv[j].x, wA.x); fma2(aH[j], xv[j].x, wA.y);
                fma2(aL[j], xv[j].y, wB.x); fma2(aH[j], xv[j].y, wB.y);
            }
        }
        __syncwarp();

        float a0[4], a1[4];
#pragma unroll
        for (int j = 0; j < 4; j++) { a0[j] = hsum2(aL[j]); a1[j] = hsum2(aH[j]); }

        // LayerNorm
        float t[4];
#pragma unroll
        for (int j = 0; j < 4; j++) t[j] = a0[j] + a1[j];
#pragma unroll
        for (int o = 16; o; o >>= 1)
#pragma unroll
            for (int j = 0; j < 4; j++) t[j] += __shfl_xor_sync(~0u, t[j], o);
        float q0[4], q1[4], vr[4];
#pragma unroll
        for (int j = 0; j < 4; j++) {
            float mu = t[j] * (1.f / 64.f);
            a0[j] -= mu; a1[j] -= mu;
            vr[j] = a0[j] * a0[j] + a1[j] * a1[j];
        }
#pragma unroll
        for (int o = 16; o; o >>= 1)
#pragma unroll
            for (int j = 0; j < 4; j++) vr[j] += __shfl_xor_sync(~0u, vr[j], o);
#pragma unroll
        for (int j = 0; j < 4; j++) {
            float rs = rsqrtf(vr[j] * (1.f / 64.f) + 1e-5f);
            q0[j] = fmaxf(fmaf(a0[j] * rs, gm.x, bt.x), 0.f);
            q1[j] = fmaxf(fmaf(a1[j] * rs, gm.y, bt.y), 0.f);
        }

        // boundary logits
        float bd[4];
#pragma unroll
        for (int j = 0; j < 4; j++) bd[j] = q0[j] * wb.x + q1[j] * wb.y;
#pragma unroll
        for (int o = 16; o; o >>= 1)
#pragma unroll
            for (int j = 0; j < 4; j++) bd[j] += __shfl_xor_sync(~0u, bd[j], o);
        if (lane == 0) {
#pragma unroll
            for (int j = 0; j < 4; j++)
                out[(size_t)13 * MPTS + p4 + j] = bd[j] + bb0;
        }

        // stage q rows
#pragma unroll
        for (int j = 0; j < 4; j++)
            *(float2*)&myS[j * 64 + 2 * lane] = make_float2(q0[j], q1[j]);
        __syncwarp();

        // Qp = q@Wq ; Kb = q@Wk ; QPE = q@Wqpe  (all pair-major, zero packs)
        unsigned long long uL[4] = {0,0,0,0}, uH[4] = {0,0,0,0};
        unsigned long long vL[4] = {0,0,0,0}, vH[4] = {0,0,0,0};
        unsigned long long cc[4] = {0,0,0,0};
#pragma unroll
        for (int Q = 0; Q < 16; Q++) {
            ulonglong2 xv[4];
#pragma unroll
            for (int j = 0; j < 4; j++)
                xv[j] = *(const ulonglong2*)&myS[j * 64 + 4 * Q];
            ulonglong2 qA = *(const ulonglong2*)&sWq[(2 * Q) * 128 + 4 * lane];
            ulonglong2 qB = *(const ulonglong2*)&sWq[(2 * Q + 1) * 128 + 4 * lane];
            ulonglong2 kA = *(const ulonglong2*)&sWk[(2 * Q) * 128 + 4 * lane];
            ulonglong2 kB2 = *(const ulonglong2*)&sWk[(2 * Q + 1) * 128 + 4 * lane];
            unsigned long long pA =
                *(const unsigned long long*)&sWqpe[(2 * Q) * 64 + 2 * lane];
            unsigned long long pB =
                *(const unsigned long long*)&sWqpe[(2 * Q + 1) * 64 + 2 * lane];
#pragma unroll
            for (int j = 0; j < 4; j++) {
                fma2(uL[j], xv[j].x, qA.x); fma2(uH[j], xv[j].x, qA.y);
                fma2(vL[j], xv[j].x, kA.x); fma2(vH[j], xv[j].x, kA.y);
                fma2(cc[j], xv[j].x, pA);
                fma2(uL[j], xv[j].y, qB.x); fma2(uH[j], xv[j].y, qB.y);
                fma2(vL[j], xv[j].y, kB2.x); fma2(vH[j], xv[j].y, kB2.y);
                fma2(cc[j], xv[j].y, pB);
            }
        }
        __syncwarp();
#pragma unroll
        for (int j = 0; j < 4; j++) {
            unsigned p = p4 + j;
            *(float2*)&g_Qp[((size_t)p << 6) + 2 * lane] =
                make_float2(hsum2(uL[j]), hsum2(uH[j]));
            g_Kbh[(p << 5) + lane] = __floats2half2_rn(hsum2(vL[j]), hsum2(vH[j]));
            g_QPE[((size_t)p << 5) + lane] = hsum2(cc[j]);
        }
    }
}

// ---------------------------------------------------------------------------
// Kernel A2: 4 points/warp.  Vo = sem @ W_vo  (pair-major FFMA2, stored fp16)
// ---------------------------------------------------------------------------
__global__ void __launch_bounds__(256) kA2(const float* __restrict__ sem)
{
    extern __shared__ float sm[];
    float* sW = sm;             // 6144 (pair-major: 48 pairs x 128)
    float* stage = sm + 6144;   // 8 warps * 384

    for (int idx = threadIdx.x; idx < 6144; idx += 256) {
        int i = idx >> 6, c = idx & 63;
        sW[(i >> 1) * 128 + c * 2 + (i & 1)] = g_Wvo[idx];
    }
    __syncthreads();

    const int lane = threadIdx.x & 31;
    float* myS = stage + (threadIdx.x >> 5) * 384;
    const int warp = (blockIdx.x * blockDim.x + threadIdx.x) >> 5;
    const int nw   = (gridDim.x * blockDim.x) >> 5;

    for (int p4 = warp * 4; p4 < MPTS; p4 += nw * 4) {
        {
            const float4* ssrc = (const float4*)(sem + (size_t)p4 * 96);
            float4* sdst = (float4*)myS;
            sdst[lane]      = ssrc[lane];
            sdst[lane + 32] = ssrc[lane + 32];
            sdst[lane + 64] = ssrc[lane + 64];
        }
        __syncwarp();

        unsigned long long oL[4] = {0,0,0,0}, oH[4] = {0,0,0,0};
#pragma unroll
        for (int Q = 0; Q < 24; Q++) {
            ulonglong2 xv[4];
#pragma unroll
            for (int j = 0; j < 4; j++)
                xv[j] = *(const ulonglong2*)&myS[j * 96 + 4 * Q];
            ulonglong2 wA = *(const ulonglong2*)&sW[(2 * Q) * 128 + 4 * lane];
            ulonglong2 wB = *(const ulonglong2*)&sW[(2 * Q + 1) * 128 + 4 * lane];
#pragma unroll
            for (int j = 0; j < 4; j++) {
                fma2(oL[j], xv[j].x, wA.x); fma2(oH[j], xv[j].x, wA.y);
                fma2(oL[j], xv[j].y, wB.x); fma2(oH[j], xv[j].y, wB.y);
            }
        }
        __syncwarp();
#pragma unroll
        for (int j = 0; j < 4; j++)
            g_Voh[((unsigned)(p4 + j) << 5) + lane] =
                __floats2half2_rn(hsum2(oL[j]), hsum2(oH[j]));
    }
}

// ---------------------------------------------------------------------------
// Kernel B: attention, 1 point/warp (unchanged from R13/R14 winner).
// ---------------------------------------------------------------------------
__global__ void __launch_bounds__(256, 5) kB(
    const int* __restrict__ nbr, const float* __restrict__ bo,
    float* __restrict__ out)
{
    __shared__ float sBo[64];
    __shared__ float sPart[8][28 * 32];   // packed rows of 32, XOR-swizzled chunks

    if (threadIdx.x < 64) sBo[threadIdx.x] = bo[threadIdx.x];
    __syncthreads();

    const int lane = threadIdx.x & 31;
    float* part = sPart[threadIdx.x >> 5];
    const int warp = (blockIdx.x * blockDim.x + threadIdx.x) >> 5;
    const int nw   = (gridDim.x * blockDim.x) >> 5;
    const float2 bo2 = *(const float2*)&sBo[2 * lane];
    const int chunk = lane >> 2, within = lane & 3;

    const size_t off_aff = (size_t)14 * MPTS;
    const size_t off_ref = (size_t)41 * MPTS;
    const size_t off_nbr = (size_t)105 * MPTS;
    const size_t off_msk = (size_t)132 * MPTS;

    for (int p = warp; p < MPTS; p += nw) {
        float2 q = *(const float2*)&g_Qp[((size_t)p << 6) + 2 * lane];
        float qpe_l = g_QPE[((size_t)p << 5) + lane];

        int cp = g_cpack[p];
        int cx = cp & 255, cy = (cp >> 8) & 255, cz = (cp >> 16) & 255;

        int packed = 0;
        if (lane < KN) {
            int idx = nbr[(size_t)p * KN + lane];
            int np = g_cpack[idx];
            int rx = (np & 255) - cx;
            int ry = ((np >> 8) & 255) - cy;
            int rz = ((np >> 16) & 255) - cz;
            int vld = (max(abs(rx), max(abs(ry), abs(rz))) <= 1);
            int pos = min(max(rx + 1, 0), 2) * 9 + min(max(ry + 1, 0), 2) * 3
                    + min(max(rz + 1, 0), 2);
            packed = idx | (pos << 17) | (vld << 22);
        }

#pragma unroll
        for (int k = 0; k < KN; k++) {
            int pk = __shfl_sync(~0u, packed, k);
            unsigned idx = (unsigned)(pk & 0x1FFFF);
            float2 kf = __half22float2(g_Kbh[(idx << 5) + lane]);
            part[(k << 5) + (((chunk ^ (k & 7)) << 2) | within)] =
                q.x * kf.x + q.y * kf.y;
        }
        __syncwarp();

        int mypos = (packed >> 17) & 31;
        float qpe_mine = __shfl_sync(~0u, qpe_l, mypos);

        float logit = -1e30f;
        if (lane < KN) {
            const float* rw = part + (lane << 5);
            int sw = lane & 7;
            float4 t0 = *(const float4*)(rw + ((0 ^ sw) << 2));
            float4 t1 = *(const float4*)(rw + ((1 ^ sw) << 2));
            float4 t2 = *(const float4*)(rw + ((2 ^ sw) << 2));
            float4 t3 = *(const float4*)(rw + ((3 ^ sw) << 2));
            float4 t4 = *(const float4*)(rw + ((4 ^ sw) << 2));
            float4 t5 = *(const float4*)(rw + ((5 ^ sw) << 2));
            float4 t6 = *(const float4*)(rw + ((6 ^ sw) << 2));
            float4 t7 = *(const float4*)(rw + ((7 ^ sw) << 2));
            float s01 = (t0.x + t0.y) + (t0.z + t0.w) + (t1.x + t1.y) + (t1.z + t1.w);
            float s23 = (t2.x + t2.y) + (t2.z + t2.w) + (t3.x + t3.y) + (t3.z + t3.w);
            float s45 = (t4.x + t4.y) + (t4.z + t4.w) + (t5.x + t5.y) + (t5.z + t5.w);
            float s67 = (t6.x + t6.y) + (t6.z + t6.w) + (t7.x + t7.y) + (t7.z + t7.w);
            float s = (s01 + s23) + (s45 + s67) + qpe_mine;
            logit = (packed >> 22) ? s * 0.125f : -10000.0f;
        }
        __syncwarp();

        float mx = logit;
#pragma unroll
        for (int o = 16; o; o >>= 1)
            mx = fmaxf(mx, __shfl_xor_sync(~0u, mx, o));
        float e = __expf(logit - mx);
        float ssum = e;
#pragma unroll
        for (int o = 16; o; o >>= 1)
            ssum += __shfl_xor_sync(~0u, ssum, o);
        float aff = e / ssum;

        float2 r = __half22float2(g_Voh[((unsigned)p << 5) + lane]);
        float2 r2 = make_float2(0.f, 0.f);
#pragma unroll
        for (int k = 0; k < KN; k += 2) {
            float aa = __shfl_sync(~0u, aff, k);
            int   pk = __shfl_sync(~0u, packed, k);
            float2 v = __half22float2(g_Voh[(((unsigned)pk & 0x1FFFFu) << 5) + lane]);
            r.x = fmaf(aa, v.x, r.x); r.y = fmaf(aa, v.y, r.y);
            if (k + 1 < KN) {
                float ab = __shfl_sync(~0u, aff, k + 1);
                int   pb = __shfl_sync(~0u, packed, k + 1);
                float2 w = __half22float2(g_Voh[(((unsigned)pb & 0x1FFFFu) << 5) + lane]);
                r2.x = fmaf(ab, w.x, r2.x); r2.y = fmaf(ab, w.y, r2.y);
            }
        }
        r.x += r2.x; r.y += r2.y;

        *(float2*)&out[off_ref + ((size_t)p << 6) + 2 * lane] =
            make_float2(r.x + bo2.x, r.y + bo2.y);
        if (lane < KN) {
            size_t a = (size_t)p * KN + lane;
            out[off_aff + a] = aff;
            out[off_nbr + a] = (float)(packed & 0x1FFFF);
            out[off_msk + a] = (packed >> 22) ? 1.f : 0.f;
        }
    }
}

// ---------------------------------------------------------------------------
// Kernel C: logits = refined_feat @ Wc + bc  (reads refined from out buffer)
// ---------------------------------------------------------------------------
__global__ void __launch_bounds__(256) kC(
    const float* __restrict__ Wc, const float* __restrict__ bc,
    float* __restrict__ out)
{
    __shared__ float sWc[832];
    __shared__ float sBc[16];
    __shared__ float stage[8 * 256];
    for (int i = threadIdx.x; i < 832; i += 256) sWc[i] = Wc[i];
    if (threadIdx.x < 16) sBc[threadIdx.x] = (threadIdx.x < 13) ? bc[threadIdx.x] : 0.f;
    __syncthreads();

    const int lane = threadIdx.x & 31;
    float* myS = stage + (threadIdx.x >> 5) * 256;
    const int warp = (blockIdx.x * blockDim.x + threadIdx.x) >> 5;
    const int nw   = (gridDim.x * blockDim.x) >> 5;
    const float* refv = out + (size_t)41 * MPTS;

    for (int p4 = warp * 4; p4 < MPTS; p4 += nw * 4) {
        {
            const float4* rs = (const float4*)(refv + (size_t)p4 * 64);
            float4* sdst = (float4*)myS;
            sdst[lane]      = rs[lane];
            sdst[lane + 32] = rs[lane + 32];
        }
        __syncwarp();

        float c[4];
#pragma unroll
        for (int j = 0; j < 4; j++) c[j] = (lane < 13) ? sBc[lane] : 0.f;
#pragma unroll
        for (int i = 0; i < 64; i += 4) {
            float xj[4][4];
#pragma unroll
            for (int j = 0; j < 4; j++) {
                float4 t = *(const float4*)&myS[j * 64 + i];
                xj[j][0] = t.x; xj[j][1] = t.y; xj[j][2] = t.z; xj[j][3] = t.w;
            }
#pragma unroll
            for (int s = 0; s < 4; s++) {
                float w = (lane < 13) ? sWc[(i + s) * 13 + lane] : 0.f;
#pragma unroll
                for (int j = 0; j < 4; j++) c[j] = fmaf(xj[j][s], w, c[j]);
            }
        }
        __syncwarp();
        if (lane < 13) {
#pragma unroll
            for (int j = 0; j < 4; j++)
                out[(size_t)(p4 + j) * 13 + lane] = c[j];
        }
    }
}

extern "C" void kernel_launch(void* const* d_in, const int* in_sizes, int n_in,
                              void* d_out, int out_size)
{
    const float* geo    = (const float*)d_in[0];
    const float* sem    = (const float*)d_in[1];
    const int*   coords = (const int*)d_in[2];
    const int*   nbr    = (const int*)d_in[3];   // int32 (JAX x64 off)
    const float* Wg     = (const float*)d_in[4];
    const float* gam    = (const float*)d_in[5];
    const float* bet    = (const float*)d_in[6];
    const float* Wb     = (const float*)d_in[7];
    const float* bb     = (const float*)d_in[8];
    const float* Wq     = (const float*)d_in[9];
    const float* Wk     = (const float*)d_in[10];
    const float* Wv     = (const float*)d_in[11];
    const float* pe     = (const float*)d_in[12];
    const float* Wo     = (const float*)d_in[13];
    const float* bo     = (const float*)d_in[14];
    const float* Wc     = (const float*)d_in[15];
    const float* bc     = (const float*)d_in[16];
    float* out = (float*)d_out;

    const int smemA1 = 16576 * 4;   // 66304 B
    const int smemA2 = 9216 * 4;    // 36864 B
    cudaFuncSetAttribute(kA1, cudaFuncAttributeMaxDynamicSharedMemorySize, smemA1);
    cudaFuncSetAttribute(kA2, cudaFuncAttributeMaxDynamicSharedMemorySize, smemA2);

    kW<<<64, 256>>>(Wv, Wo, Wq, pe, coords);
    kA1<<<592, 256, smemA1>>>(geo, Wg, gam, bet, Wb, bb, Wq, Wk, out);
    kA2<<<592, 256, smemA2>>>(sem);
    kB<<<12500, 256>>>(nbr, bo, out);
    kC<<<592, 256>>>(Wc, bc, out);
}